// round 1
// baseline (speedup 1.0000x reference)
#include <cuda_runtime.h>

#define B_   8
#define H_   16
#define S_   1024
#define D_   64
#define BH_  (B_*H_)
#define ROWS 32
#define CT   256
#define NT   256

#define OUT_O_ELEMS (BH_*S_*D_)       /* 8,388,608  */
#define OUT_W_ELEMS (BH_*S_*S_)       /* 134,217,728 */

// smem: q_s[32][64] | kv_s[64][256] (reused as v[128][64]) | sc_s[32][1024]
#define SMEM_FLOATS (ROWS*D_ + 64*CT + ROWS*S_)

__global__ void __launch_bounds__(NT, 1)
attn_fused_kernel(const float* __restrict__ q, const float* __restrict__ k,
                  const float* __restrict__ v, const float* __restrict__ prev,
                  const float* __restrict__ mask, const float* __restrict__ scale_p,
                  float* __restrict__ out, int write_ws)
{
    extern __shared__ float smem[];
    float* q_s  = smem;                    // [ROWS][D_]
    float* kv_s = q_s + ROWS*D_;           // [64][CT] / [128][64]
    float* sc_s = kv_s + 64*CT;            // [ROWS][S_]

    const int tid  = threadIdx.x;
    const int bh   = blockIdx.x / (S_/ROWS);
    const int rb   = blockIdx.x % (S_/ROWS);
    const int row0 = rb * ROWS;
    const float scale = *scale_p;

    const float* qb = q    + (size_t)bh*S_*D_;
    const float* kb = k    + (size_t)bh*D_*S_;
    const float* vb = v    + (size_t)bh*S_*D_;
    const float* pb = prev + (size_t)bh*S_*S_;
    float* outO = out;
    float* outW = out + (size_t)OUT_O_ELEMS;
    float* outS = outW + (size_t)OUT_W_ELEMS;

    // ---- load Q tile: 2048 floats = 512 float4 ----
    {
        const float4* src = (const float4*)(qb + (size_t)row0*D_);
        float4* dst = (float4*)q_s;
        dst[tid]      = src[tid];
        dst[tid + NT] = src[tid + NT];
    }

    const int ty = tid >> 5;   // warp id 0..7  -> rows ty*4..ty*4+3
    const int tx = tid & 31;   // lane          -> cols tx*4 (+0 / +128)

    // ================= GEMM1: scores = Q @ K =================
    for (int st = 0; st < S_; st += CT) {
        __syncthreads();
        // load K tile [64][CT]: 4096 float4
        #pragma unroll
        for (int it = 0; it < (64*CT/4)/NT; it++) {
            int slot = tid + it*NT;
            int d  = slot >> 6;        // CT/4 = 64 float4 per row
            int c4 = slot & 63;
            *(float4*)(kv_s + d*CT + c4*4) =
                *(const float4*)(kb + (size_t)d*S_ + st + c4*4);
        }
        __syncthreads();

        float acc[4][8];
        #pragma unroll
        for (int i = 0; i < 4; i++)
            #pragma unroll
            for (int j = 0; j < 8; j++) acc[i][j] = 0.f;

        #pragma unroll 8
        for (int kk = 0; kk < D_; kk++) {
            float4 kA = *(float4*)(kv_s + kk*CT + tx*4);
            float4 kB = *(float4*)(kv_s + kk*CT + 128 + tx*4);
            #pragma unroll
            for (int i = 0; i < 4; i++) {
                float qv = q_s[(ty*4 + i)*D_ + kk];
                acc[i][0] += qv*kA.x; acc[i][1] += qv*kA.y;
                acc[i][2] += qv*kA.z; acc[i][3] += qv*kA.w;
                acc[i][4] += qv*kB.x; acc[i][5] += qv*kB.y;
                acc[i][6] += qv*kB.z; acc[i][7] += qv*kB.w;
            }
        }

        // epilogue: s = acc*mask*scale + prev ; write gmem scores + smem
        #pragma unroll
        for (int i = 0; i < 4; i++) {
            int r    = ty*4 + i;
            int qrow = row0 + r;
            size_t moff = (size_t)qrow*S_ + st + tx*4;
            float4 mA = *(const float4*)(mask + moff);
            float4 mB = *(const float4*)(mask + moff + 128);
            float4 pA = *(const float4*)(pb + moff);
            float4 pB = *(const float4*)(pb + moff + 128);
            float4 sA, sB;
            sA.x = acc[i][0]*mA.x*scale + pA.x;
            sA.y = acc[i][1]*mA.y*scale + pA.y;
            sA.z = acc[i][2]*mA.z*scale + pA.z;
            sA.w = acc[i][3]*mA.w*scale + pA.w;
            sB.x = acc[i][4]*mB.x*scale + pB.x;
            sB.y = acc[i][5]*mB.y*scale + pB.y;
            sB.z = acc[i][6]*mB.z*scale + pB.z;
            sB.w = acc[i][7]*mB.w*scale + pB.w;
            if (write_ws) {
                *(float4*)(outS + (size_t)bh*S_*S_ + moff)       = sA;
                *(float4*)(outS + (size_t)bh*S_*S_ + moff + 128) = sB;
            }
            *(float4*)(sc_s + r*S_ + st + tx*4)       = sA;
            *(float4*)(sc_s + r*S_ + st + 128 + tx*4) = sB;
        }
    }
    __syncthreads();

    // ================= softmax: each warp owns 4 rows =================
    #pragma unroll
    for (int i = 0; i < 4; i++) {
        int r = ty*4 + i;
        float4* rowp = (float4*)(sc_s + r*S_);
        float4 vals[8];
        float m = -1e30f;
        #pragma unroll
        for (int j = 0; j < 8; j++) {
            vals[j] = rowp[tx + j*32];
            m = fmaxf(m, fmaxf(fmaxf(vals[j].x, vals[j].y), fmaxf(vals[j].z, vals[j].w)));
        }
        #pragma unroll
        for (int off = 16; off; off >>= 1)
            m = fmaxf(m, __shfl_xor_sync(0xffffffffu, m, off));
        float sum = 0.f;
        #pragma unroll
        for (int j = 0; j < 8; j++) {
            vals[j].x = __expf(vals[j].x - m);
            vals[j].y = __expf(vals[j].y - m);
            vals[j].z = __expf(vals[j].z - m);
            vals[j].w = __expf(vals[j].w - m);
            sum += vals[j].x + vals[j].y + vals[j].z + vals[j].w;
        }
        #pragma unroll
        for (int off = 16; off; off >>= 1)
            sum += __shfl_xor_sync(0xffffffffu, sum, off);
        float inv = 1.0f / sum;
        int qrow = row0 + r;
        float4* wrow = (float4*)(outW + (size_t)bh*S_*S_ + (size_t)qrow*S_);
        #pragma unroll
        for (int j = 0; j < 8; j++) {
            vals[j].x *= inv; vals[j].y *= inv; vals[j].z *= inv; vals[j].w *= inv;
            rowp[tx + j*32] = vals[j];
            if (write_ws) wrow[tx + j*32] = vals[j];
        }
    }

    // ================= GEMM2: O = W @ V =================
    const int tx16 = tid & 15;    // cols tx16*4
    const int ty16 = tid >> 4;    // rows ty16*2..+1
    float o[2][4] = {};
    for (int sb = 0; sb < S_; sb += 128) {
        __syncthreads();
        // load V tile [128][64]: 2048 float4
        #pragma unroll
        for (int it = 0; it < 8; it++) {
            int slot = tid + it*NT;
            int sr = slot >> 4;
            int c4 = slot & 15;
            *(float4*)(kv_s + sr*64 + c4*4) =
                *(const float4*)(vb + (size_t)(sb + sr)*D_ + c4*4);
        }
        __syncthreads();
        #pragma unroll 8
        for (int kk = 0; kk < 128; kk++) {
            float4 vv = *(float4*)(kv_s + kk*64 + tx16*4);
            float w0 = sc_s[(ty16*2    )*S_ + sb + kk];
            float w1 = sc_s[(ty16*2 + 1)*S_ + sb + kk];
            o[0][0] += w0*vv.x; o[0][1] += w0*vv.y; o[0][2] += w0*vv.z; o[0][3] += w0*vv.w;
            o[1][0] += w1*vv.x; o[1][1] += w1*vv.y; o[1][2] += w1*vv.z; o[1][3] += w1*vv.w;
        }
    }
    #pragma unroll
    for (int i = 0; i < 2; i++) {
        int qrow = row0 + ty16*2 + i;
        *(float4*)(outO + (size_t)bh*S_*D_ + (size_t)qrow*D_ + tx16*4) =
            make_float4(o[i][0], o[i][1], o[i][2], o[i][3]);
    }
}

extern "C" void kernel_launch(void* const* d_in, const int* in_sizes, int n_in,
                              void* d_out, int out_size)
{
    const float* q     = (const float*)d_in[0];
    const float* k     = (const float*)d_in[1];
    const float* v     = (const float*)d_in[2];
    const float* prev  = (const float*)d_in[3];
    const float* mask  = (const float*)d_in[4];
    const float* scale = (const float*)d_in[5];
    float* out = (float*)d_out;

    // Does the harness want all three tuple outputs, or just the first?
    int write_ws = (out_size >= (int)0) ? 1 : 1;
    {
        long long need = (long long)OUT_O_ELEMS + 2LL*OUT_W_ELEMS;
        write_ws = ((long long)out_size >= need) ? 1 : 0;
    }

    size_t smem = (size_t)SMEM_FLOATS * sizeof(float);  // 200 KB
    cudaFuncSetAttribute(attn_fused_kernel,
                         cudaFuncAttributeMaxDynamicSharedMemorySize, (int)smem);

    dim3 grid(BH_ * (S_/ROWS));
    attn_fused_kernel<<<grid, NT, smem>>>(q, k, v, prev, mask, scale, out, write_ws);
}

// round 2
// speedup vs baseline: 1.0044x; 1.0044x over previous
#include <cuda_runtime.h>

#define B_   8
#define H_   16
#define S_   1024
#define D_   64
#define BH_  (B_*H_)
#define ROWS 32
#define CT   256
#define NT   256

#define OUT_O_ELEMS (BH_*S_*D_)       /* 8,388,608  */
#define OUT_W_ELEMS (BH_*S_*S_)       /* 134,217,728 */

// smem: q_s[32][64] | kv_s[64][256] (reused as v[128][64]) | sc_s[32][1024]
#define SMEM_FLOATS (ROWS*D_ + 64*CT + ROWS*S_)

__global__ void __launch_bounds__(NT, 1)
attn_fused_kernel(const float* __restrict__ q, const float* __restrict__ k,
                  const float* __restrict__ v, const float* __restrict__ prev,
                  const float* __restrict__ mask, const float* __restrict__ scale_p,
                  float* __restrict__ out, int write_ws)
{
    extern __shared__ float smem[];
    float* q_s  = smem;                    // [ROWS][D_]
    float* kv_s = q_s + ROWS*D_;           // [64][CT] / [128][64]
    float* sc_s = kv_s + 64*CT;            // [ROWS][S_]

    const int tid  = threadIdx.x;
    const int bh   = blockIdx.x / (S_/ROWS);
    const int rb   = blockIdx.x % (S_/ROWS);
    const int row0 = rb * ROWS;
    const float scale = *scale_p;

    const float* qb = q    + (size_t)bh*S_*D_;
    const float* kb = k    + (size_t)bh*D_*S_;
    const float* vb = v    + (size_t)bh*S_*D_;
    const float* pb = prev + (size_t)bh*S_*S_;
    float* outO = out;
    float* outW = out + (size_t)OUT_O_ELEMS;
    float* outS = outW + (size_t)OUT_W_ELEMS;

    // ---- load Q tile: 2048 floats = 512 float4 ----
    {
        const float4* src = (const float4*)(qb + (size_t)row0*D_);
        float4* dst = (float4*)q_s;
        dst[tid]      = src[tid];
        dst[tid + NT] = src[tid + NT];
    }

    const int ty = tid >> 5;   // warp id 0..7  -> rows ty*4..ty*4+3
    const int tx = tid & 31;   // lane          -> cols tx*4 (+0 / +128)

    // ================= GEMM1: scores = Q @ K =================
    for (int st = 0; st < S_; st += CT) {
        __syncthreads();
        // load K tile [64][CT]: 4096 float4
        #pragma unroll
        for (int it = 0; it < (64*CT/4)/NT; it++) {
            int slot = tid + it*NT;
            int d  = slot >> 6;        // CT/4 = 64 float4 per row
            int c4 = slot & 63;
            *(float4*)(kv_s + d*CT + c4*4) =
                *(const float4*)(kb + (size_t)d*S_ + st + c4*4);
        }
        __syncthreads();

        float acc[4][8];
        #pragma unroll
        for (int i = 0; i < 4; i++)
            #pragma unroll
            for (int j = 0; j < 8; j++) acc[i][j] = 0.f;

        #pragma unroll 8
        for (int kk = 0; kk < D_; kk++) {
            float4 kA = *(float4*)(kv_s + kk*CT + tx*4);
            float4 kB = *(float4*)(kv_s + kk*CT + 128 + tx*4);
            #pragma unroll
            for (int i = 0; i < 4; i++) {
                float qv = q_s[(ty*4 + i)*D_ + kk];
                acc[i][0] += qv*kA.x; acc[i][1] += qv*kA.y;
                acc[i][2] += qv*kA.z; acc[i][3] += qv*kA.w;
                acc[i][4] += qv*kB.x; acc[i][5] += qv*kB.y;
                acc[i][6] += qv*kB.z; acc[i][7] += qv*kB.w;
            }
        }

        // epilogue: s = acc*mask*scale + prev ; write gmem scores + smem
        #pragma unroll
        for (int i = 0; i < 4; i++) {
            int r    = ty*4 + i;
            int qrow = row0 + r;
            size_t moff = (size_t)qrow*S_ + st + tx*4;
            float4 mA = *(const float4*)(mask + moff);
            float4 mB = *(const float4*)(mask + moff + 128);
            float4 pA = *(const float4*)(pb + moff);
            float4 pB = *(const float4*)(pb + moff + 128);
            float4 sA, sB;
            sA.x = acc[i][0]*mA.x*scale + pA.x;
            sA.y = acc[i][1]*mA.y*scale + pA.y;
            sA.z = acc[i][2]*mA.z*scale + pA.z;
            sA.w = acc[i][3]*mA.w*scale + pA.w;
            sB.x = acc[i][4]*mB.x*scale + pB.x;
            sB.y = acc[i][5]*mB.y*scale + pB.y;
            sB.z = acc[i][6]*mB.z*scale + pB.z;
            sB.w = acc[i][7]*mB.w*scale + pB.w;
            if (write_ws) {
                *(float4*)(outS + (size_t)bh*S_*S_ + moff)       = sA;
                *(float4*)(outS + (size_t)bh*S_*S_ + moff + 128) = sB;
            }
            *(float4*)(sc_s + r*S_ + st + tx*4)       = sA;
            *(float4*)(sc_s + r*S_ + st + 128 + tx*4) = sB;
        }
    }
    __syncthreads();

    // ================= softmax: each warp owns 4 rows =================
    #pragma unroll
    for (int i = 0; i < 4; i++) {
        int r = ty*4 + i;
        float4* rowp = (float4*)(sc_s + r*S_);
        float4 vals[8];
        float m = -1e30f;
        #pragma unroll
        for (int j = 0; j < 8; j++) {
            vals[j] = rowp[tx + j*32];
            m = fmaxf(m, fmaxf(fmaxf(vals[j].x, vals[j].y), fmaxf(vals[j].z, vals[j].w)));
        }
        #pragma unroll
        for (int off = 16; off; off >>= 1)
            m = fmaxf(m, __shfl_xor_sync(0xffffffffu, m, off));
        float sum = 0.f;
        #pragma unroll
        for (int j = 0; j < 8; j++) {
            vals[j].x = __expf(vals[j].x - m);
            vals[j].y = __expf(vals[j].y - m);
            vals[j].z = __expf(vals[j].z - m);
            vals[j].w = __expf(vals[j].w - m);
            sum += vals[j].x + vals[j].y + vals[j].z + vals[j].w;
        }
        #pragma unroll
        for (int off = 16; off; off >>= 1)
            sum += __shfl_xor_sync(0xffffffffu, sum, off);
        float inv = 1.0f / sum;
        int qrow = row0 + r;
        float4* wrow = (float4*)(outW + (size_t)bh*S_*S_ + (size_t)qrow*S_);
        #pragma unroll
        for (int j = 0; j < 8; j++) {
            vals[j].x *= inv; vals[j].y *= inv; vals[j].z *= inv; vals[j].w *= inv;
            rowp[tx + j*32] = vals[j];
            if (write_ws) wrow[tx + j*32] = vals[j];
        }
    }

    // ================= GEMM2: O = W @ V =================
    const int tx16 = tid & 15;    // cols tx16*4
    const int ty16 = tid >> 4;    // rows ty16*2..+1
    float o[2][4] = {};
    for (int sb = 0; sb < S_; sb += 128) {
        __syncthreads();
        // load V tile [128][64]: 2048 float4
        #pragma unroll
        for (int it = 0; it < 8; it++) {
            int slot = tid + it*NT;
            int sr = slot >> 4;
            int c4 = slot & 15;
            *(float4*)(kv_s + sr*64 + c4*4) =
                *(const float4*)(vb + (size_t)(sb + sr)*D_ + c4*4);
        }
        __syncthreads();
        #pragma unroll 8
        for (int kk = 0; kk < 128; kk++) {
            float4 vv = *(float4*)(kv_s + kk*64 + tx16*4);
            float w0 = sc_s[(ty16*2    )*S_ + sb + kk];
            float w1 = sc_s[(ty16*2 + 1)*S_ + sb + kk];
            o[0][0] += w0*vv.x; o[0][1] += w0*vv.y; o[0][2] += w0*vv.z; o[0][3] += w0*vv.w;
            o[1][0] += w1*vv.x; o[1][1] += w1*vv.y; o[1][2] += w1*vv.z; o[1][3] += w1*vv.w;
        }
    }
    #pragma unroll
    for (int i = 0; i < 2; i++) {
        int qrow = row0 + ty16*2 + i;
        *(float4*)(outO + (size_t)bh*S_*D_ + (size_t)qrow*D_ + tx16*4) =
            make_float4(o[i][0], o[i][1], o[i][2], o[i][3]);
    }
}

extern "C" void kernel_launch(void* const* d_in, const int* in_sizes, int n_in,
                              void* d_out, int out_size)
{
    const float* q     = (const float*)d_in[0];
    const float* k     = (const float*)d_in[1];
    const float* v     = (const float*)d_in[2];
    const float* prev  = (const float*)d_in[3];
    const float* mask  = (const float*)d_in[4];
    const float* scale = (const float*)d_in[5];
    float* out = (float*)d_out;

    // Does the harness want all three tuple outputs, or just the first?
    int write_ws = (out_size >= (int)0) ? 1 : 1;
    {
        long long need = (long long)OUT_O_ELEMS + 2LL*OUT_W_ELEMS;
        write_ws = ((long long)out_size >= need) ? 1 : 0;
    }

    size_t smem = (size_t)SMEM_FLOATS * sizeof(float);  // 200 KB
    cudaFuncSetAttribute(attn_fused_kernel,
                         cudaFuncAttributeMaxDynamicSharedMemorySize, (int)smem);

    dim3 grid(BH_ * (S_/ROWS));
    attn_fused_kernel<<<grid, NT, smem>>>(q, k, v, prev, mask, scale, out, write_ws);
}

// round 5
// speedup vs baseline: 1.4409x; 1.4346x over previous
#include <cuda_runtime.h>
#include <cuda.h>
#include <cstdint>

#define B_   8
#define H_   16
#define S_   1024
#define D_   64
#define BH_  (B_*H_)
#define NT   256
#define NCHUNK_A (S_/128)   // 8
#define NCHUNK_B (S_/64)    // 16

#define OUT_O ((size_t)BH_*S_*D_)
#define OUT_W ((size_t)BH_*S_*S_)

__device__ float g_Kt[BH_*S_*D_];   // Kt[bh][s][d]
__device__ float g_Vt[BH_*D_*S_];   // Vt[bh][d][s]

// ---- smem offsets (from 1KB-aligned base) ----
// Phase A: QH 32K | QL 32K | KH 2x32K | KL 2x32K
#define OFF_QH   0u
#define OFF_QL   32768u
#define OFF_KH   65536u
#define OFF_KL   131072u
// Phase B overlays: WH 2x16K | WL 2x16K | VH 2x16K | VL 2x16K
#define OFF_WH   0u
#define OFF_WL   32768u
#define OFF_VH   65536u
#define OFF_VL   98304u
#define OFF_MISC 196608u
#define OFF_TM   (OFF_MISC + 0u)
#define OFF_KB0  (OFF_MISC + 8u)
#define OFF_KB1  (OFF_MISC + 16u)
#define OFF_VB0  (OFF_MISC + 24u)
#define OFF_VB1  (OFF_MISC + 32u)
#define OFF_MB   (OFF_MISC + 40u)
#define OFF_LP   (OFF_MISC + 64u)
#define SMEM_BYTES (OFF_MISC + 64u + 1024u + 1024u)

// idesc tf32: dtype f32(1<<4), atype TF32(2<<7), btype TF32(2<<10), N/8<<17, M/16<<24
#define IDESC_N128 ((1u<<4)|(2u<<7)|(2u<<10)|((128u/8u)<<17)|((128u/16u)<<24))
#define IDESC_N64  ((1u<<4)|(2u<<7)|(2u<<10)|(( 64u/8u)<<17)|((128u/16u)<<24))

#define SWZ(o) ((o) ^ (((o) >> 3) & 0x70u))
#define TF32_MASK 0xFFFFE000u

#if defined(__CUDA_ARCH_FEAT_SM103_ALL) || defined(__CUDA_ARCH_FEAT_SM100_ALL)
#define HAS_TC 1
#endif

__device__ __forceinline__ uint32_t smem_u32(const void* p) {
    uint32_t a;
    asm("{ .reg .u64 t; cvta.to.shared.u64 t, %1; cvt.u32.u64 %0, t; }" : "=r"(a) : "l"(p));
    return a;
}
#define MBAR_INIT(a, n) asm volatile("mbarrier.init.shared.b64 [%0], %1;" :: "r"(a), "r"(n) : "memory")
#define MBAR_EXPECT(a, b) asm volatile("mbarrier.arrive.expect_tx.shared.b64 _, [%0], %1;" :: "r"(a), "r"(b) : "memory")
#define MBAR_WAIT(a, ph) do { \
    uint32_t _m = (a), _p = (ph), _d; \
    asm volatile("{ .reg .pred p; mbarrier.try_wait.parity.acquire.cta.shared::cta.b64 p, [%1], %2; selp.b32 %0,1,0,p; }" \
        : "=r"(_d) : "r"(_m), "r"(_p) : "memory"); \
    if (!_d) { \
        asm volatile("{ .reg .pred P1;\nWL_%=:\n mbarrier.try_wait.parity.acquire.cta.shared::cta.b64 P1, [%0], %1, 0x989680;\n @P1 bra.uni WD_%=;\n bra.uni WL_%=;\nWD_%=:\n}" \
            :: "r"(_m), "r"(_p) : "memory"); \
    } } while (0)
#define TMA_LD2D(dst, map, x, y, bar) \
    asm volatile("cp.async.bulk.tensor.2d.shared::cta.global.tile.mbarrier::complete_tx::bytes [%0], [%1, {%2, %3}], [%4];" \
        :: "r"(dst), "l"(map), "r"(x), "r"(y), "r"(bar) : "memory")
#define FENCE_ASYNC() asm volatile("fence.proxy.async.shared::cta;" ::: "memory")

#ifdef HAS_TC
#define TC_ALLOC(a, n) asm volatile("tcgen05.alloc.cta_group::1.sync.aligned.shared::cta.b32 [%0], %1;" :: "r"(a), "r"(n) : "memory")
#define TC_RELINQ()    asm volatile("tcgen05.relinquish_alloc_permit.cta_group::1.sync.aligned;")
#define TC_DEALLOC(t, n) asm volatile("tcgen05.dealloc.cta_group::1.sync.aligned.b32 %0, %1;" :: "r"(t), "r"(n))
#define TC_COMMIT(bar) asm volatile("tcgen05.commit.cta_group::1.mbarrier::arrive::one.shared::cluster.b64 [%0];" :: "r"(bar) : "memory")
#define TC_WAIT_LD() asm volatile("tcgen05.wait::ld.sync.aligned;" ::: "memory")
#define TC_FENCE_BEFORE() asm volatile("tcgen05.fence::before_thread_sync;" ::: "memory")
#define TC_FENCE_AFTER()  asm volatile("tcgen05.fence::after_thread_sync;" ::: "memory")
#define TC_LD_X32(r, addr) \
    asm volatile("tcgen05.ld.sync.aligned.32x32b.x32.b32 " \
        "{%0,%1,%2,%3,%4,%5,%6,%7,%8,%9,%10,%11,%12,%13,%14,%15," \
        "%16,%17,%18,%19,%20,%21,%22,%23,%24,%25,%26,%27,%28,%29,%30,%31}, [%32];" \
        : "=r"((r)[0]),"=r"((r)[1]),"=r"((r)[2]),"=r"((r)[3]),"=r"((r)[4]),"=r"((r)[5]),"=r"((r)[6]),"=r"((r)[7]), \
          "=r"((r)[8]),"=r"((r)[9]),"=r"((r)[10]),"=r"((r)[11]),"=r"((r)[12]),"=r"((r)[13]),"=r"((r)[14]),"=r"((r)[15]), \
          "=r"((r)[16]),"=r"((r)[17]),"=r"((r)[18]),"=r"((r)[19]),"=r"((r)[20]),"=r"((r)[21]),"=r"((r)[22]),"=r"((r)[23]), \
          "=r"((r)[24]),"=r"((r)[25]),"=r"((r)[26]),"=r"((r)[27]),"=r"((r)[28]),"=r"((r)[29]),"=r"((r)[30]),"=r"((r)[31]) \
        : "r"(addr))

__device__ __forceinline__ void mma_tf32_ss(uint32_t d, uint64_t a, uint64_t b,
                                            uint32_t idesc, uint32_t en) {
    asm volatile("{\n\t.reg .pred p;\n\tsetp.ne.u32 p, %4, 0;\n\t"
                 "tcgen05.mma.cta_group::1.kind::tf32 [%0], %1, %2, %3, {%5,%5,%5,%5}, p;\n\t}"
                 :: "r"(d), "l"(a), "l"(b), "r"(idesc), "r"(en), "r"(0u) : "memory");
}
#endif

static __device__ __forceinline__ uint64_t mk_desc(uint32_t addr) {
    return (uint64_t(2) << 61) | (uint64_t(1) << 46) | (uint64_t(64) << 32) | (uint64_t(1) << 16)
         | ((uint64_t)(addr >> 4) & 0x3FFFull);
}
__device__ __forceinline__ float4 lo4(float4 h) {
    float4 l;
    l.x = h.x - __uint_as_float(__float_as_uint(h.x) & TF32_MASK);
    l.y = h.y - __uint_as_float(__float_as_uint(h.y) & TF32_MASK);
    l.z = h.z - __uint_as_float(__float_as_uint(h.z) & TF32_MASK);
    l.w = h.w - __uint_as_float(__float_as_uint(h.w) & TF32_MASK);
    return l;
}
__device__ __forceinline__ float4 hi4(float4 f) {
    float4 h;
    h.x = __uint_as_float(__float_as_uint(f.x) & TF32_MASK);
    h.y = __uint_as_float(__float_as_uint(f.y) & TF32_MASK);
    h.z = __uint_as_float(__float_as_uint(f.z) & TF32_MASK);
    h.w = __uint_as_float(__float_as_uint(f.w) & TF32_MASK);
    return h;
}

// ===================== transpose pre-pass =====================
__global__ void transpose_kv(const float* __restrict__ k, const float* __restrict__ v) {
    __shared__ float t[32][33];
    int bh = blockIdx.z;
    int which = blockIdx.y >> 1;
    int d_tile = blockIdx.y & 1;
    int s_tile = blockIdx.x;
    int tx = threadIdx.x, ty = threadIdx.y;
    if (which == 0) {
        const float* kb = k + (size_t)bh * D_ * S_;
        #pragma unroll
        for (int i = 0; i < 4; i++) {
            int dy = ty + i * 8;
            t[tx][dy] = kb[(size_t)(d_tile * 32 + dy) * S_ + s_tile * 32 + tx];
        }
        __syncthreads();
        float* ktb = g_Kt + (size_t)bh * S_ * D_;
        #pragma unroll
        for (int i = 0; i < 4; i++) {
            int sy = ty + i * 8;
            ktb[(size_t)(s_tile * 32 + sy) * D_ + d_tile * 32 + tx] = t[sy][tx];
        }
    } else {
        const float* vb = v + (size_t)bh * S_ * D_;
        #pragma unroll
        for (int i = 0; i < 4; i++) {
            int sy = ty + i * 8;
            t[tx][sy] = vb[(size_t)(s_tile * 32 + sy) * D_ + d_tile * 32 + tx];
        }
        __syncthreads();
        float* vtb = g_Vt + (size_t)bh * D_ * S_;
        #pragma unroll
        for (int i = 0; i < 4; i++) {
            int dy = ty + i * 8;
            vtb[(size_t)(d_tile * 32 + dy) * S_ + s_tile * 32 + tx] = t[dy][tx];
        }
    }
}

// ===================== main fused attention =====================
__global__ void __launch_bounds__(NT, 1) __cluster_dims__(1, 1, 1)
attn_main(const float* __restrict__ prev, const float* __restrict__ mask,
          const float* __restrict__ scale_p, float* __restrict__ out,
          const __grid_constant__ CUtensorMap qmap,
          const __grid_constant__ CUtensorMap kmap,
          const __grid_constant__ CUtensorMap vmap)
{
#ifdef HAS_TC
    extern __shared__ char smraw[];
    const uint32_t sb0 = smem_u32(smraw);
    const uint32_t sbase = (sb0 + 1023u) & ~1023u;
    char* sm = smraw + (sbase - sb0);

    const int tid = threadIdx.x;
    const int wid = tid >> 5;
    const int wg  = wid >> 2;
    const int r   = ((wid & 3) << 5) | (tid & 31);
    const int bh  = blockIdx.x >> 3;
    const int qb  = (blockIdx.x & 7) * 128;
    const float scale = *scale_p;
    const size_t growR = (size_t)bh * S_ + qb + r;

    float* outO = out;
    float* outW = out + OUT_O;
    float* outS = outW + OUT_W;
    float* lpart = (float*)(sm + OFF_LP);

    if (tid == 0) {
        MBAR_INIT(sbase + OFF_KB0, 1);
        MBAR_INIT(sbase + OFF_KB1, 1);
        MBAR_INIT(sbase + OFF_VB0, 1);
        MBAR_INIT(sbase + OFF_VB1, 1);
        MBAR_INIT(sbase + OFF_MB, 1);
    }
    if (wid == 0) { TC_ALLOC(sbase + OFF_TM, 512); TC_RELINQ(); }
    __syncthreads();
    uint32_t tmem;
    asm volatile("ld.shared.b32 %0, [%1];" : "=r"(tmem) : "r"(sbase + OFF_TM));
    const uint32_t TM_D = tmem;
    const uint32_t TM_O = tmem + 128;

    // prologue: Q + K chunk0 -> KB0 ; K chunk1 -> KB1
    if (tid == 0) {
        int row0 = bh * S_ + qb;
        MBAR_EXPECT(sbase + OFF_KB0, 65536);
        TMA_LD2D(sbase + OFF_QH,          &qmap, 0,  row0, sbase + OFF_KB0);
        TMA_LD2D(sbase + OFF_QH + 16384,  &qmap, 32, row0, sbase + OFF_KB0);
        TMA_LD2D(sbase + OFF_KH,          &kmap, 0,  bh * S_,     sbase + OFF_KB0);
        TMA_LD2D(sbase + OFF_KH + 16384,  &kmap, 32, bh * S_,     sbase + OFF_KB0);
        MBAR_EXPECT(sbase + OFF_KB1, 32768);
        TMA_LD2D(sbase + OFF_KH + 32768,          &kmap, 0,  bh * S_ + 128, sbase + OFF_KB1);
        TMA_LD2D(sbase + OFF_KH + 32768 + 16384,  &kmap, 32, bh * S_ + 128, sbase + OFF_KB1);
    }

    int mph = 0;
    float l_acc = 0.0f;
    uint32_t dr[32];

    // =============== Phase A: raw scores + row sums (3xTF32) ===============
    for (int c = 0; c < NCHUNK_A; c++) {
        const uint32_t kbar   = (c & 1) ? (sbase + OFF_KB1) : (sbase + OFF_KB0);
        const uint32_t khslot = OFF_KH + (uint32_t)(c & 1) * 32768u;
        const uint32_t klslot = OFF_KL + (uint32_t)(c & 1) * 32768u;
        __syncthreads();
        TC_FENCE_AFTER();
        MBAR_WAIT(kbar, (c >> 1) & 1);
        // compute lo tiles (and Q_lo once)
        {
            const float4* src = (const float4*)(sm + khslot);
            float4* dst = (float4*)(sm + klslot);
            #pragma unroll
            for (int j = 0; j < 8; j++) { int i = tid + j * NT; dst[i] = lo4(src[i]); }
            if (c == 0) {
                const float4* qs = (const float4*)(sm + OFF_QH);
                float4* qd = (float4*)(sm + OFF_QL);
                #pragma unroll
                for (int j = 0; j < 8; j++) { int i = tid + j * NT; qd[i] = lo4(qs[i]); }
            }
        }
        FENCE_ASYNC();
        __syncthreads();
        if (tid == 0) {
            const uint32_t aoffs[3] = { sbase + OFF_QH, sbase + OFF_QH, sbase + OFF_QL };
            const uint32_t boffs[3] = { sbase + khslot, sbase + klslot, sbase + khslot };
            #pragma unroll
            for (int term = 0; term < 3; term++) {
                #pragma unroll
                for (int t = 0; t < 8; t++) {
                    uint64_t ad = mk_desc(aoffs[term] + (uint32_t)(t >> 2) * 16384u) + (uint64_t)(t & 3) * 2;
                    uint64_t bd = mk_desc(boffs[term] + (uint32_t)(t >> 2) * 16384u) + (uint64_t)(t & 3) * 2;
                    mma_tf32_ss(TM_D, ad, bd, IDESC_N128, (term > 0 || t > 0) ? 1u : 0u);
                }
            }
            TC_COMMIT(sbase + OFF_MB);
        }
        MBAR_WAIT(sbase + OFF_MB, mph); mph ^= 1;
        TC_FENCE_AFTER();
        if (tid == 0 && c + 2 < NCHUNK_A) {
            MBAR_EXPECT(kbar, 32768);
            TMA_LD2D(sbase + khslot,          &kmap, 0,  bh * S_ + (c + 2) * 128, kbar);
            TMA_LD2D(sbase + khslot + 16384,  &kmap, 32, bh * S_ + (c + 2) * 128, kbar);
        }
        #pragma unroll
        for (int g2 = 0; g2 < 2; g2++) {
            int g = wg * 2 + g2;
            int c0 = g * 32;
            TC_LD_X32(dr, TM_D + c0);
            TC_WAIT_LD();
            const float4* pv = (const float4*)(prev + growR * S_ + c * 128 + c0);
            const float4* mk = (const float4*)(mask + ((size_t)(qb + r)) * S_ + c * 128 + c0);
            float4* so = (float4*)(outS + growR * S_ + c * 128 + c0);
            #pragma unroll
            for (int j = 0; j < 8; j++) {
                float4 p = pv[j], m = mk[j], s;
                s.x = __uint_as_float(dr[4*j+0]) * m.x * scale + p.x;
                s.y = __uint_as_float(dr[4*j+1]) * m.y * scale + p.y;
                s.z = __uint_as_float(dr[4*j+2]) * m.z * scale + p.z;
                s.w = __uint_as_float(dr[4*j+3]) * m.w * scale + p.w;
                so[j] = s;
                l_acc += __expf(s.x) + __expf(s.y) + __expf(s.z) + __expf(s.w);
            }
        }
        TC_FENCE_BEFORE();
    }

    lpart[wg * 128 + r] = l_acc;
    __syncthreads();
    const float inv_l = 1.0f / (lpart[r] + lpart[128 + r]);

    // prologue: V chunks 0,1 (64 s-cols each)
    if (tid == 0) {
        #pragma unroll
        for (int s0 = 0; s0 < 2; s0++) {
            uint32_t vbar = sbase + (s0 ? OFF_VB1 : OFF_VB0);
            uint32_t vh = sbase + OFF_VH + (uint32_t)s0 * 16384u;
            MBAR_EXPECT(vbar, 16384);
            TMA_LD2D(vh,         &vmap, s0 * 64,      bh * D_, vbar);
            TMA_LD2D(vh + 8192,  &vmap, s0 * 64 + 32, bh * D_, vbar);
        }
    }

    // =============== Phase B: W = exp(s)/l, O += W @ Vt (3xTF32) ===============
    for (int c = 0; c < NCHUNK_B; c++) {
        const uint32_t vbar = (c & 1) ? (sbase + OFF_VB1) : (sbase + OFF_VB0);
        const uint32_t vh = OFF_VH + (uint32_t)(c & 1) * 16384u;
        const uint32_t vl = OFF_VL + (uint32_t)(c & 1) * 16384u;
        MBAR_WAIT(vbar, (c >> 1) & 1);
        // V_lo
        {
            const float4* src = (const float4*)(sm + vh);
            float4* dst = (float4*)(sm + vl);
            #pragma unroll
            for (int j = 0; j < 4; j++) { int i = tid + j * NT; dst[i] = lo4(src[i]); }
        }
        // W for this wg's 32 cols
        {
            int cbase = c * 64 + wg * 32;
            const float4* sv = (const float4*)(outS + growR * S_ + cbase);
            float4* wo = (float4*)(outW + growR * S_ + cbase);
            char* sh = sm + OFF_WH + (uint32_t)wg * 16384u;
            char* sl = sm + OFF_WL + (uint32_t)wg * 16384u;
            #pragma unroll
            for (int j = 0; j < 8; j++) {
                float4 s = sv[j], w;
                w.x = __expf(s.x) * inv_l;
                w.y = __expf(s.y) * inv_l;
                w.z = __expf(s.z) * inv_l;
                w.w = __expf(s.w) * inv_l;
                wo[j] = w;
                uint32_t off = (uint32_t)r * 128u + (uint32_t)j * 16u;
                float4 h = hi4(w);
                *(float4*)(sh + SWZ(off)) = h;
                float4 l = make_float4(w.x - h.x, w.y - h.y, w.z - h.z, w.w - h.w);
                *(float4*)(sl + SWZ(off)) = l;
            }
        }
        FENCE_ASYNC();
        __syncthreads();
        if (tid == 0) {
            const uint32_t aoffs[3] = { sbase + OFF_WH, sbase + OFF_WH, sbase + OFF_WL };
            const uint32_t boffs[3] = { sbase + vh, sbase + vl, sbase + vh };
            #pragma unroll
            for (int term = 0; term < 3; term++) {
                #pragma unroll
                for (int t = 0; t < 8; t++) {
                    uint64_t ad = mk_desc(aoffs[term] + (uint32_t)(t >> 2) * 16384u) + (uint64_t)(t & 3) * 2;
                    uint64_t bd = mk_desc(boffs[term] + (uint32_t)(t >> 2) * 8192u) + (uint64_t)(t & 3) * 2;
                    mma_tf32_ss(TM_O, ad, bd, IDESC_N64, (c > 0 || term > 0 || t > 0) ? 1u : 0u);
                }
            }
            TC_COMMIT(sbase + OFF_MB);
        }
        MBAR_WAIT(sbase + OFF_MB, mph); mph ^= 1;
        if (tid == 0 && c + 2 < NCHUNK_B) {
            MBAR_EXPECT(vbar, 16384);
            TMA_LD2D(sbase + vh,         &vmap, (c + 2) * 64,      bh * D_, vbar);
            TMA_LD2D(sbase + vh + 8192,  &vmap, (c + 2) * 64 + 32, bh * D_, vbar);
        }
        __syncthreads();   // all threads see MMA done before staging overwrite next iter
    }

    // =============== O writeback (warpgroup 0) ===============
    TC_FENCE_AFTER();
    if (wg == 0) {
        uint32_t o0[32], o1[32];
        TC_LD_X32(o0, TM_O);
        TC_LD_X32(o1, TM_O + 32);
        TC_WAIT_LD();
        float4* oo = (float4*)(outO + growR * D_);
        #pragma unroll
        for (int j = 0; j < 8; j++) {
            oo[j]     = make_float4(__uint_as_float(o0[4*j]), __uint_as_float(o0[4*j+1]),
                                    __uint_as_float(o0[4*j+2]), __uint_as_float(o0[4*j+3]));
            oo[8 + j] = make_float4(__uint_as_float(o1[4*j]), __uint_as_float(o1[4*j+1]),
                                    __uint_as_float(o1[4*j+2]), __uint_as_float(o1[4*j+3]));
        }
    }
    TC_FENCE_BEFORE();
    __syncthreads();
    if (wid == 0) TC_DEALLOC(tmem, 512);
#endif  // HAS_TC
}

// ===================== host side =====================
typedef CUresult (*PFN_tmap)(CUtensorMap*, CUtensorMapDataType, cuuint32_t, void*,
                             const cuuint64_t*, const cuuint64_t*, const cuuint32_t*,
                             const cuuint32_t*, CUtensorMapInterleave, CUtensorMapSwizzle,
                             CUtensorMapL2promotion, CUtensorMapFloatOOBfill);

static void make_map(PFN_tmap enc, CUtensorMap* m, void* ptr,
                     uint64_t d0, uint64_t d1, uint64_t rowBytes,
                     uint32_t b0, uint32_t b1)
{
    cuuint64_t dims[2] = {d0, d1};
    cuuint64_t strides[1] = {rowBytes};
    cuuint32_t box[2] = {b0, b1};
    cuuint32_t es[2] = {1, 1};
    enc(m, CU_TENSOR_MAP_DATA_TYPE_FLOAT32, 2, ptr, dims, strides, box, es,
        CU_TENSOR_MAP_INTERLEAVE_NONE, CU_TENSOR_MAP_SWIZZLE_128B,
        CU_TENSOR_MAP_L2_PROMOTION_L2_128B, CU_TENSOR_MAP_FLOAT_OOB_FILL_NONE);
}

extern "C" void kernel_launch(void* const* d_in, const int* in_sizes, int n_in,
                              void* d_out, int out_size)
{
    const float* q     = (const float*)d_in[0];
    const float* k     = (const float*)d_in[1];
    const float* v     = (const float*)d_in[2];
    const float* prev  = (const float*)d_in[3];
    const float* mask  = (const float*)d_in[4];
    const float* scale = (const float*)d_in[5];
    float* out = (float*)d_out;

    PFN_tmap enc = nullptr;
    cudaDriverEntryPointQueryResult st;
    cudaGetDriverEntryPoint("cuTensorMapEncodeTiled", (void**)&enc, cudaEnableDefault, &st);

    void* ktp = nullptr; void* vtp = nullptr;
    cudaGetSymbolAddress(&ktp, g_Kt);
    cudaGetSymbolAddress(&vtp, g_Vt);

    CUtensorMap qmap, kmap, vmap;
    make_map(enc, &qmap, (void*)q, D_, (uint64_t)BH_ * S_, D_ * 4, 32, 128);
    make_map(enc, &kmap, ktp,      D_, (uint64_t)BH_ * S_, D_ * 4, 32, 128);
    make_map(enc, &vmap, vtp,      S_, (uint64_t)BH_ * D_, S_ * 4, 32, 64);

    dim3 tb(32, 8), tg(32, 4, BH_);
    transpose_kv<<<tg, tb>>>(k, v);

    cudaFuncSetAttribute(attn_main, cudaFuncAttributeMaxDynamicSharedMemorySize, SMEM_BYTES);
    attn_main<<<BH_ * 8, NT, SMEM_BYTES>>>(prev, mask, scale, out, qmap, kmap, vmap);
}

// round 6
// speedup vs baseline: 2.0404x; 1.4161x over previous
#include <cuda_runtime.h>
#include <cuda_bf16.h>
#include <cstdint>

#define B_   8
#define H_   16
#define S_   1024
#define D_   64
#define BH_  (B_*H_)
#define NT   256
#define NCH  16            // 64-col chunks

#define OUT_O ((size_t)BH_*S_*D_)
#define OUT_W ((size_t)BH_*S_*S_)

__device__ float g_Kt[BH_*S_*D_];   // Kt[bh][s][d]
__device__ float g_Vt[BH_*D_*S_];   // Vt[bh][d][s]

// ---- smem (from 1KB-aligned base) ----
#define OFF_A0   0u        // Q0 | W0 (16K bf16 [128][64])
#define OFF_A1   16384u    // Q1 | W1
#define OFF_B    32768u    // K bufs: buf b at +b*16K (K0 8K, K1 8K). Phase B: V0/V1 at +0/+8K
#define OFF_MISC 65536u
#define OFF_TM    (OFF_MISC + 0u)
#define OFF_MMA0  (OFF_MISC + 8u)
#define OFF_MMA1  (OFF_MISC + 16u)
#define OFF_CONS0 (OFF_MISC + 24u)
#define OFF_CONS1 (OFF_MISC + 32u)
#define OFF_MMA2  (OFF_MISC + 40u)
#define OFF_LP    (OFF_MISC + 64u)   // float[256]
#define SMEM_BYTES (OFF_MISC + 64u + 1024u + 1024u)

// idesc bf16 (kind::f16): dtype f32(1<<4), atype BF16(1<<7), btype BF16(1<<10), N/8<<17, M/16<<24
#define IDESC_BF16_N64 ((1u<<4)|(1u<<7)|(1u<<10)|(8u<<17)|(8u<<24))

#define SWZ(o) ((o) ^ (((o) >> 3) & 0x70u))

#if defined(__CUDA_ARCH_FEAT_SM103_ALL) || defined(__CUDA_ARCH_FEAT_SM100_ALL)
#define HAS_TC 1
#endif

__device__ __forceinline__ uint32_t smem_u32(const void* p) {
    uint32_t a;
    asm("{ .reg .u64 t; cvta.to.shared.u64 t, %1; cvt.u32.u64 %0, t; }" : "=r"(a) : "l"(p));
    return a;
}
#define MBAR_INIT(a, n) asm volatile("mbarrier.init.shared.b64 [%0], %1;" :: "r"(a), "r"(n) : "memory")
#define MBAR_ARRIVE(a)  asm volatile("mbarrier.arrive.shared.b64 _, [%0];" :: "r"(a) : "memory")
#define MBAR_WAIT(a, ph) do { \
    uint32_t _m = (a), _p = (ph), _d; \
    asm volatile("{ .reg .pred p; mbarrier.try_wait.parity.acquire.cta.shared::cta.b64 p, [%1], %2; selp.b32 %0,1,0,p; }" \
        : "=r"(_d) : "r"(_m), "r"(_p) : "memory"); \
    if (!_d) { \
        asm volatile("{ .reg .pred P1;\nWL_%=:\n mbarrier.try_wait.parity.acquire.cta.shared::cta.b64 P1, [%0], %1, 0x989680;\n @P1 bra.uni WD_%=;\n bra.uni WL_%=;\nWD_%=:\n}" \
            :: "r"(_m), "r"(_p) : "memory"); \
    } } while (0)
#define FENCE_ASYNC() asm volatile("fence.proxy.async.shared::cta;" ::: "memory")

#ifdef HAS_TC
#define TC_ALLOC(a, n) asm volatile("tcgen05.alloc.cta_group::1.sync.aligned.shared::cta.b32 [%0], %1;" :: "r"(a), "r"(n) : "memory")
#define TC_RELINQ()    asm volatile("tcgen05.relinquish_alloc_permit.cta_group::1.sync.aligned;")
#define TC_DEALLOC(t, n) asm volatile("tcgen05.dealloc.cta_group::1.sync.aligned.b32 %0, %1;" :: "r"(t), "r"(n))
#define TC_COMMIT(bar) asm volatile("tcgen05.commit.cta_group::1.mbarrier::arrive::one.shared::cluster.b64 [%0];" :: "r"(bar) : "memory")
#define TC_WAIT_LD() asm volatile("tcgen05.wait::ld.sync.aligned;" ::: "memory")
#define TC_FENCE_BEFORE() asm volatile("tcgen05.fence::before_thread_sync;" ::: "memory")
#define TC_FENCE_AFTER()  asm volatile("tcgen05.fence::after_thread_sync;" ::: "memory")
#define TC_LD_X32(r, addr) \
    asm volatile("tcgen05.ld.sync.aligned.32x32b.x32.b32 " \
        "{%0,%1,%2,%3,%4,%5,%6,%7,%8,%9,%10,%11,%12,%13,%14,%15," \
        "%16,%17,%18,%19,%20,%21,%22,%23,%24,%25,%26,%27,%28,%29,%30,%31}, [%32];" \
        : "=r"((r)[0]),"=r"((r)[1]),"=r"((r)[2]),"=r"((r)[3]),"=r"((r)[4]),"=r"((r)[5]),"=r"((r)[6]),"=r"((r)[7]), \
          "=r"((r)[8]),"=r"((r)[9]),"=r"((r)[10]),"=r"((r)[11]),"=r"((r)[12]),"=r"((r)[13]),"=r"((r)[14]),"=r"((r)[15]), \
          "=r"((r)[16]),"=r"((r)[17]),"=r"((r)[18]),"=r"((r)[19]),"=r"((r)[20]),"=r"((r)[21]),"=r"((r)[22]),"=r"((r)[23]), \
          "=r"((r)[24]),"=r"((r)[25]),"=r"((r)[26]),"=r"((r)[27]),"=r"((r)[28]),"=r"((r)[29]),"=r"((r)[30]),"=r"((r)[31]) \
        : "r"(addr))

__device__ __forceinline__ void mma_bf16_ss(uint32_t d, uint64_t a, uint64_t b, uint32_t en) {
    asm volatile("{\n\t.reg .pred p;\n\tsetp.ne.u32 p, %4, 0;\n\t"
                 "tcgen05.mma.cta_group::1.kind::f16 [%0], %1, %2, %3, {%5,%5,%5,%5}, p;\n\t}"
                 :: "r"(d), "l"(a), "l"(b), "r"(IDESC_BF16_N64), "r"(en), "r"(0u) : "memory");
}
#endif

static __device__ __forceinline__ uint64_t mk_desc(uint32_t addr) {
    return (uint64_t(2) << 61) | (uint64_t(1) << 46) | (uint64_t(64) << 32) | (uint64_t(1) << 16)
         | ((uint64_t)(addr >> 4) & 0x3FFFull);
}

#ifdef HAS_TC
// issue 3-term bf16x3 MMA: A0B0 (+A0B1 +A1B0), K=64 via 4 steps of 16
__device__ __forceinline__ void issue_mma3(uint32_t dtm, uint32_t a0, uint32_t a1,
                                           uint32_t b0, uint32_t b1, uint32_t accum_first) {
    uint64_t A0 = mk_desc(a0), A1 = mk_desc(a1), B0 = mk_desc(b0), B1 = mk_desc(b1);
    #pragma unroll
    for (int t = 0; t < 4; t++) mma_bf16_ss(dtm, A0 + t*2, B0 + t*2, (t > 0) ? 1u : accum_first);
    #pragma unroll
    for (int t = 0; t < 4; t++) mma_bf16_ss(dtm, A0 + t*2, B1 + t*2, 1u);
    #pragma unroll
    for (int t = 0; t < 4; t++) mma_bf16_ss(dtm, A1 + t*2, B0 + t*2, 1u);
}
#endif

// split f32 pair -> bf16 hi word + bf16 lo word
__device__ __forceinline__ void cvt2(float x, float y, uint32_t& hw, uint32_t& lw) {
    __nv_bfloat162 h = __floats2bfloat162_rn(x, y);
    float hx = __bfloat162float(h.x), hy = __bfloat162float(h.y);
    __nv_bfloat162 l = __floats2bfloat162_rn(x - hx, y - hy);
    hw = *(uint32_t*)&h;
    lw = *(uint32_t*)&l;
}
__device__ __forceinline__ void stage4(float4 f, char* p0, char* p1, uint32_t off) {
    uint32_t h0, l0, h1, l1;
    cvt2(f.x, f.y, h0, l0);
    cvt2(f.z, f.w, h1, l1);
    uint32_t so = SWZ(off);
    *(uint2*)(p0 + so) = make_uint2(h0, h1);
    *(uint2*)(p1 + so) = make_uint2(l0, l1);
}

// ===================== transpose pre-pass =====================
__global__ void transpose_kv(const float* __restrict__ k, const float* __restrict__ v) {
    __shared__ float t[32][33];
    int bh = blockIdx.z;
    int which = blockIdx.y >> 1;
    int d_tile = blockIdx.y & 1;
    int s_tile = blockIdx.x;
    int tx = threadIdx.x, ty = threadIdx.y;
    if (which == 0) {
        const float* kb = k + (size_t)bh * D_ * S_;
        #pragma unroll
        for (int i = 0; i < 4; i++) {
            int dy = ty + i * 8;
            t[tx][dy] = kb[(size_t)(d_tile * 32 + dy) * S_ + s_tile * 32 + tx];
        }
        __syncthreads();
        float* ktb = g_Kt + (size_t)bh * S_ * D_;
        #pragma unroll
        for (int i = 0; i < 4; i++) {
            int sy = ty + i * 8;
            ktb[(size_t)(s_tile * 32 + sy) * D_ + d_tile * 32 + tx] = t[sy][tx];
        }
    } else {
        const float* vb = v + (size_t)bh * S_ * D_;
        #pragma unroll
        for (int i = 0; i < 4; i++) {
            int sy = ty + i * 8;
            t[tx][sy] = vb[(size_t)(s_tile * 32 + sy) * D_ + d_tile * 32 + tx];
        }
        __syncthreads();
        float* vtb = g_Vt + (size_t)bh * D_ * S_;
        #pragma unroll
        for (int i = 0; i < 4; i++) {
            int dy = ty + i * 8;
            vtb[(size_t)(d_tile * 32 + dy) * S_ + s_tile * 32 + tx] = t[dy][tx];
        }
    }
}

// ===================== main fused attention =====================
__global__ void __launch_bounds__(NT, 2)
attn_main(const float* __restrict__ q, const float* __restrict__ prev,
          const float* __restrict__ mask, const float* __restrict__ scale_p,
          float* __restrict__ out)
{
#ifdef HAS_TC
    extern __shared__ char smraw[];
    const uint32_t sb0 = smem_u32(smraw);
    const uint32_t sbase = (sb0 + 1023u) & ~1023u;
    char* sm = smraw + (sbase - sb0);

    const int tid = threadIdx.x;
    const int wid = tid >> 5;
    const int wg  = wid >> 2;                       // warpgroup 0/1 -> cols wg*32
    const int r   = ((wid & 3) << 5) | (tid & 31);  // TMEM lane / row 0..127
    const int bh  = blockIdx.x >> 3;
    const int qb  = (blockIdx.x & 7) * 128;
    const float scale = *scale_p;
    const size_t growR = (size_t)bh * S_ + qb + r;

    float* outO = out;
    float* outW = out + OUT_O;
    float* outS = outW + OUT_W;
    float* lpart = (float*)(sm + OFF_LP);

    const float4* qp4  = (const float4*)(q + ((size_t)bh * S_ + qb) * D_);
    const float4* ktp4 = (const float4*)(g_Kt + (size_t)bh * S_ * D_);
    const float*  vtb  = g_Vt + (size_t)bh * D_ * S_;

    if (tid == 0) {
        MBAR_INIT(sbase + OFF_MMA0, 1);
        MBAR_INIT(sbase + OFF_MMA1, 1);
        MBAR_INIT(sbase + OFF_CONS0, NT);
        MBAR_INIT(sbase + OFF_CONS1, NT);
        MBAR_INIT(sbase + OFF_MMA2, 1);
    }
    if (wid == 0) { TC_ALLOC(sbase + OFF_TM, 256); TC_RELINQ(); }
    __syncthreads();
    uint32_t tmem;
    asm volatile("ld.shared.b32 %0, [%1];" : "=r"(tmem) : "r"(sbase + OFF_TM));
    const uint32_t TM_D = tmem;         // 2 x 64 cols ping-pong
    const uint32_t TM_O = tmem + 128;   // 64 cols

    // ---- prefetch K chunk 0, then stage Q (bf16x2 split) ----
    float4 kreg[4];
    #pragma unroll
    for (int j = 0; j < 4; j++) kreg[j] = ktp4[tid + j * NT];
    #pragma unroll
    for (int j = 0; j < 8; j++) {
        int i = tid + j * NT;
        stage4(qp4[i], sm + OFF_A0, sm + OFF_A1, (uint32_t)i * 8u);
    }

    int phm0 = 0, phm1 = 0, phc0 = 0, phc1 = 0;
    float l_acc = 0.0f;

    // =============== Phase A: pipelined scores ===============
    for (int c = 0; c <= NCH; c++) {
        if (c < NCH) {
            const int b = c & 1;
            char* k0 = sm + OFF_B + (uint32_t)b * 16384u;
            char* k1 = k0 + 8192;
            #pragma unroll
            for (int j = 0; j < 4; j++)
                stage4(kreg[j], k0, k1, (uint32_t)(tid + j * NT) * 8u);
            if (c + 1 < NCH) {
                #pragma unroll
                for (int j = 0; j < 4; j++)
                    kreg[j] = ktp4[(c + 1) * 1024 + tid + j * NT];
            }
            FENCE_ASYNC();
            __syncthreads();
            if (tid == 0) {
                if (c >= 2) {
                    if (b == 0) { MBAR_WAIT(sbase + OFF_CONS0, phc0); phc0 ^= 1; }
                    else        { MBAR_WAIT(sbase + OFF_CONS1, phc1); phc1 ^= 1; }
                }
                issue_mma3(TM_D + (uint32_t)b * 64u,
                           sbase + OFF_A0, sbase + OFF_A1,
                           sbase + OFF_B + (uint32_t)b * 16384u,
                           sbase + OFF_B + (uint32_t)b * 16384u + 8192u, 0u);
                TC_COMMIT(sbase + ((b == 0) ? OFF_MMA0 : OFF_MMA1));
            }
        }
        if (c >= 1) {
            const int cc = c - 1, b2 = cc & 1;
            const float4* pvp = (const float4*)(prev + growR * S_ + cc * 64 + wg * 32);
            const float4* mkp = (const float4*)(mask + (size_t)(qb + r) * S_ + cc * 64 + wg * 32);
            float4 pv[8], mk[8];
            #pragma unroll
            for (int j = 0; j < 8; j++) pv[j] = pvp[j];
            #pragma unroll
            for (int j = 0; j < 8; j++) mk[j] = mkp[j];
            if (b2 == 0) { MBAR_WAIT(sbase + OFF_MMA0, phm0); phm0 ^= 1; }
            else         { MBAR_WAIT(sbase + OFF_MMA1, phm1); phm1 ^= 1; }
            TC_FENCE_AFTER();
            uint32_t dr[32];
            TC_LD_X32(dr, TM_D + (uint32_t)b2 * 64u + (uint32_t)wg * 32u);
            TC_WAIT_LD();
            float4* so = (float4*)(outS + growR * S_ + cc * 64 + wg * 32);
            #pragma unroll
            for (int j = 0; j < 8; j++) {
                float4 s;
                s.x = __uint_as_float(dr[4*j+0]) * mk[j].x * scale + pv[j].x;
                s.y = __uint_as_float(dr[4*j+1]) * mk[j].y * scale + pv[j].y;
                s.z = __uint_as_float(dr[4*j+2]) * mk[j].z * scale + pv[j].z;
                s.w = __uint_as_float(dr[4*j+3]) * mk[j].w * scale + pv[j].w;
                so[j] = s;
                l_acc += __expf(s.x) + __expf(s.y) + __expf(s.z) + __expf(s.w);
            }
            TC_FENCE_BEFORE();
            MBAR_ARRIVE(sbase + ((b2 == 0) ? OFF_CONS0 : OFF_CONS1));
        }
    }

    lpart[wg * 128 + r] = l_acc;
    __syncthreads();
    const float inv_l = 1.0f / (lpart[r] + lpart[128 + r]);

    // =============== Phase B: W + O (reverse order for L2) ===============
    // prefetch S and V for chunk 15
    float4 sreg[8], vreg[4];
    {
        const float4* sp = (const float4*)(outS + growR * S_ + 15 * 64 + wg * 32);
        #pragma unroll
        for (int j = 0; j < 8; j++) sreg[j] = sp[j];
        #pragma unroll
        for (int j = 0; j < 4; j++) {
            int i = tid + j * NT;
            int row = i >> 4, quad = i & 15;
            vreg[j] = *(const float4*)(vtb + (size_t)row * S_ + 15 * 64 + quad * 4);
        }
    }
    int ph2 = 0;
    for (int idx = 0; idx < NCH; idx++) {
        const int c = 15 - idx;
        // compute W (gmem write) from prefetched S
        float4 w[8];
        float4* wo = (float4*)(outW + growR * S_ + c * 64 + wg * 32);
        #pragma unroll
        for (int j = 0; j < 8; j++) {
            w[j].x = __expf(sreg[j].x) * inv_l;
            w[j].y = __expf(sreg[j].y) * inv_l;
            w[j].z = __expf(sreg[j].z) * inv_l;
            w[j].w = __expf(sreg[j].w) * inv_l;
            wo[j] = w[j];
        }
        // wait previous MMA2 before overwriting staging
        if (idx > 0) { MBAR_WAIT(sbase + OFF_MMA2, ph2); ph2 ^= 1; }
        // stage W (A operand) and V (B operand)
        #pragma unroll
        for (int j = 0; j < 8; j++)
            stage4(w[j], sm + OFF_A0, sm + OFF_A1,
                   (uint32_t)r * 128u + (uint32_t)wg * 64u + (uint32_t)j * 8u);
        #pragma unroll
        for (int j = 0; j < 4; j++)
            stage4(vreg[j], sm + OFF_B, sm + OFF_B + 8192, (uint32_t)(tid + j * NT) * 8u);
        // prefetch next chunk
        if (idx + 1 < NCH) {
            const float4* sp = (const float4*)(outS + growR * S_ + (c - 1) * 64 + wg * 32);
            #pragma unroll
            for (int j = 0; j < 8; j++) sreg[j] = sp[j];
            #pragma unroll
            for (int j = 0; j < 4; j++) {
                int i = tid + j * NT;
                int row = i >> 4, quad = i & 15;
                vreg[j] = *(const float4*)(vtb + (size_t)row * S_ + (c - 1) * 64 + quad * 4);
            }
        }
        FENCE_ASYNC();
        __syncthreads();
        if (tid == 0) {
            issue_mma3(TM_O, sbase + OFF_A0, sbase + OFF_A1,
                       sbase + OFF_B, sbase + OFF_B + 8192u, (idx == 0) ? 0u : 1u);
            TC_COMMIT(sbase + OFF_MMA2);
        }
    }

    // =============== O writeback ===============
    MBAR_WAIT(sbase + OFF_MMA2, ph2);
    TC_FENCE_AFTER();
    {
        uint32_t o[32];
        TC_LD_X32(o, TM_O + (uint32_t)wg * 32u);
        TC_WAIT_LD();
        float4* oo = (float4*)(outO + growR * D_ + wg * 32);
        #pragma unroll
        for (int j = 0; j < 8; j++)
            oo[j] = make_float4(__uint_as_float(o[4*j]), __uint_as_float(o[4*j+1]),
                                __uint_as_float(o[4*j+2]), __uint_as_float(o[4*j+3]));
    }
    TC_FENCE_BEFORE();
    __syncthreads();
    if (wid == 0) TC_DEALLOC(tmem, 256);
#endif  // HAS_TC
}

extern "C" void kernel_launch(void* const* d_in, const int* in_sizes, int n_in,
                              void* d_out, int out_size)
{
    const float* q     = (const float*)d_in[0];
    const float* k     = (const float*)d_in[1];
    const float* v     = (const float*)d_in[2];
    const float* prev  = (const float*)d_in[3];
    const float* mask  = (const float*)d_in[4];
    const float* scale = (const float*)d_in[5];
    float* out = (float*)d_out;

    dim3 tb(32, 8), tg(32, 4, BH_);
    transpose_kv<<<tg, tb>>>(k, v);

    cudaFuncSetAttribute(attn_main, cudaFuncAttributeMaxDynamicSharedMemorySize, SMEM_BYTES);
    attn_main<<<BH_ * 8, NT, SMEM_BYTES>>>(q, prev, mask, scale, out);
}

// round 8
// speedup vs baseline: 2.5702x; 1.2596x over previous
#include <cuda_runtime.h>
#include <cuda_bf16.h>
#include <cstdint>

#define B_   8
#define H_   16
#define S_   1024
#define D_   64
#define BH_  (B_*H_)
#define NT   256
#define NCH  16            // 64-col chunks

#define OUT_O ((size_t)BH_*S_*D_)
#define OUT_W ((size_t)BH_*S_*S_)

__device__ float g_Kt[BH_*S_*D_];   // Kt[bh][s][d]
__device__ float g_Vt[BH_*D_*S_];   // Vt[bh][d][s]

// ---- smem (from 1KB-aligned base) ----
#define OFF_A0   0u        // Q0 | W0 (16K bf16 [128][64])
#define OFF_A1   16384u    // Q1 | W1
#define OFF_B    32768u    // K/V bufs: buf b at +b*16K (hi 8K, lo 8K)
#define OFF_DT   65536u    // D transpose tile: 128 x 65 f32 = 33280 B
#define OFF_MISC 98816u
#define OFF_TM    (OFF_MISC + 0u)
#define OFF_MMA0  (OFF_MISC + 8u)
#define OFF_MMA1  (OFF_MISC + 16u)
#define OFF_CONS0 (OFF_MISC + 24u)
#define OFF_CONS1 (OFF_MISC + 32u)
#define OFF_MMA2  (OFF_MISC + 40u)
#define OFF_LS    (OFF_MISC + 64u)   // float[128] row sums -> inv
#define SMEM_BYTES (OFF_MISC + 64u + 512u + 1024u)

// idesc bf16 (kind::f16): dtype f32(1<<4), atype BF16(1<<7), btype BF16(1<<10), N/8<<17, M/16<<24
#define IDESC_BF16_N64 ((1u<<4)|(1u<<7)|(1u<<10)|(8u<<17)|(8u<<24))

#define SWZ(o) ((o) ^ (((o) >> 3) & 0x70u))

#if defined(__CUDA_ARCH_FEAT_SM103_ALL) || defined(__CUDA_ARCH_FEAT_SM100_ALL)
#define HAS_TC 1
#endif

__device__ __forceinline__ uint32_t smem_u32(const void* p) {
    uint32_t a;
    asm("{ .reg .u64 t; cvta.to.shared.u64 t, %1; cvt.u32.u64 %0, t; }" : "=r"(a) : "l"(p));
    return a;
}
#define MBAR_INIT(a, n) asm volatile("mbarrier.init.shared.b64 [%0], %1;" :: "r"(a), "r"(n) : "memory")
#define MBAR_ARRIVE(a)  asm volatile("mbarrier.arrive.shared.b64 _, [%0];" :: "r"(a) : "memory")
#define MBAR_WAIT(a, ph) do { \
    uint32_t _m = (a), _p = (ph), _d; \
    asm volatile("{ .reg .pred p; mbarrier.try_wait.parity.acquire.cta.shared::cta.b64 p, [%1], %2; selp.b32 %0,1,0,p; }" \
        : "=r"(_d) : "r"(_m), "r"(_p) : "memory"); \
    if (!_d) { \
        asm volatile("{ .reg .pred P1;\nWL_%=:\n mbarrier.try_wait.parity.acquire.cta.shared::cta.b64 P1, [%0], %1, 0x989680;\n @P1 bra.uni WD_%=;\n bra.uni WL_%=;\nWD_%=:\n}" \
            :: "r"(_m), "r"(_p) : "memory"); \
    } } while (0)
#define FENCE_ASYNC() asm volatile("fence.proxy.async.shared::cta;" ::: "memory")
#define PREF_L2(p) asm volatile("prefetch.global.L2 [%0];" :: "l"(p))

#ifdef HAS_TC
#define TC_ALLOC(a, n) asm volatile("tcgen05.alloc.cta_group::1.sync.aligned.shared::cta.b32 [%0], %1;" :: "r"(a), "r"(n) : "memory")
#define TC_RELINQ()    asm volatile("tcgen05.relinquish_alloc_permit.cta_group::1.sync.aligned;")
#define TC_DEALLOC(t, n) asm volatile("tcgen05.dealloc.cta_group::1.sync.aligned.b32 %0, %1;" :: "r"(t), "r"(n))
#define TC_COMMIT(bar) asm volatile("tcgen05.commit.cta_group::1.mbarrier::arrive::one.shared::cluster.b64 [%0];" :: "r"(bar) : "memory")
#define TC_WAIT_LD() asm volatile("tcgen05.wait::ld.sync.aligned;" ::: "memory")
#define TC_FENCE_BEFORE() asm volatile("tcgen05.fence::before_thread_sync;" ::: "memory")
#define TC_FENCE_AFTER()  asm volatile("tcgen05.fence::after_thread_sync;" ::: "memory")
#define TC_LD_X32(r, addr) \
    asm volatile("tcgen05.ld.sync.aligned.32x32b.x32.b32 " \
        "{%0,%1,%2,%3,%4,%5,%6,%7,%8,%9,%10,%11,%12,%13,%14,%15," \
        "%16,%17,%18,%19,%20,%21,%22,%23,%24,%25,%26,%27,%28,%29,%30,%31}, [%32];" \
        : "=r"((r)[0]),"=r"((r)[1]),"=r"((r)[2]),"=r"((r)[3]),"=r"((r)[4]),"=r"((r)[5]),"=r"((r)[6]),"=r"((r)[7]), \
          "=r"((r)[8]),"=r"((r)[9]),"=r"((r)[10]),"=r"((r)[11]),"=r"((r)[12]),"=r"((r)[13]),"=r"((r)[14]),"=r"((r)[15]), \
          "=r"((r)[16]),"=r"((r)[17]),"=r"((r)[18]),"=r"((r)[19]),"=r"((r)[20]),"=r"((r)[21]),"=r"((r)[22]),"=r"((r)[23]), \
          "=r"((r)[24]),"=r"((r)[25]),"=r"((r)[26]),"=r"((r)[27]),"=r"((r)[28]),"=r"((r)[29]),"=r"((r)[30]),"=r"((r)[31]) \
        : "r"(addr))

__device__ __forceinline__ void mma_bf16_ss(uint32_t d, uint64_t a, uint64_t b, uint32_t en) {
    asm volatile("{\n\t.reg .pred p;\n\tsetp.ne.u32 p, %4, 0;\n\t"
                 "tcgen05.mma.cta_group::1.kind::f16 [%0], %1, %2, %3, {%5,%5,%5,%5}, p;\n\t}"
                 :: "r"(d), "l"(a), "l"(b), "r"(IDESC_BF16_N64), "r"(en), "r"(0u) : "memory");
}
#endif

static __device__ __forceinline__ uint64_t mk_desc(uint32_t addr) {
    return (uint64_t(2) << 61) | (uint64_t(1) << 46) | (uint64_t(64) << 32) | (uint64_t(1) << 16)
         | ((uint64_t)(addr >> 4) & 0x3FFFull);
}

#ifdef HAS_TC
// 3-term bf16x3 MMA: A0B0 + A0B1 + A1B0, K=64 via 4 steps of 16
__device__ __forceinline__ void issue_mma3(uint32_t dtm, uint32_t a0, uint32_t a1,
                                           uint32_t b0, uint32_t b1, uint32_t accum_first) {
    uint64_t A0 = mk_desc(a0), A1 = mk_desc(a1), B0 = mk_desc(b0), B1 = mk_desc(b1);
    #pragma unroll
    for (int t = 0; t < 4; t++) mma_bf16_ss(dtm, A0 + t*2, B0 + t*2, (t > 0) ? 1u : accum_first);
    #pragma unroll
    for (int t = 0; t < 4; t++) mma_bf16_ss(dtm, A0 + t*2, B1 + t*2, 1u);
    #pragma unroll
    for (int t = 0; t < 4; t++) mma_bf16_ss(dtm, A1 + t*2, B0 + t*2, 1u);
}
#endif

// split f32 pair -> bf16 hi word + bf16 lo word
__device__ __forceinline__ void cvt2(float x, float y, uint32_t& hw, uint32_t& lw) {
    __nv_bfloat162 h = __floats2bfloat162_rn(x, y);
    float hx = __bfloat162float(h.x), hy = __bfloat162float(h.y);
    __nv_bfloat162 l = __floats2bfloat162_rn(x - hx, y - hy);
    hw = *(uint32_t*)&h;
    lw = *(uint32_t*)&l;
}
__device__ __forceinline__ void stage4(float4 f, char* p0, char* p1, uint32_t off) {
    uint32_t h0, l0, h1, l1;
    cvt2(f.x, f.y, h0, l0);
    cvt2(f.z, f.w, h1, l1);
    uint32_t so = SWZ(off);
    *(uint2*)(p0 + so) = make_uint2(h0, h1);
    *(uint2*)(p1 + so) = make_uint2(l0, l1);
}

// ===================== transpose pre-pass =====================
__global__ void transpose_kv(const float* __restrict__ k, const float* __restrict__ v) {
    __shared__ float t[32][33];
    int bh = blockIdx.z;
    int which = blockIdx.y >> 1;
    int d_tile = blockIdx.y & 1;
    int s_tile = blockIdx.x;
    int tx = threadIdx.x, ty = threadIdx.y;
    if (which == 0) {
        const float* kb = k + (size_t)bh * D_ * S_;
        #pragma unroll
        for (int i = 0; i < 4; i++) {
            int dy = ty + i * 8;
            t[tx][dy] = kb[(size_t)(d_tile * 32 + dy) * S_ + s_tile * 32 + tx];
        }
        __syncthreads();
        float* ktb = g_Kt + (size_t)bh * S_ * D_;
        #pragma unroll
        for (int i = 0; i < 4; i++) {
            int sy = ty + i * 8;
            ktb[(size_t)(s_tile * 32 + sy) * D_ + d_tile * 32 + tx] = t[sy][tx];
        }
    } else {
        const float* vb = v + (size_t)bh * S_ * D_;
        #pragma unroll
        for (int i = 0; i < 4; i++) {
            int sy = ty + i * 8;
            t[tx][sy] = vb[(size_t)(s_tile * 32 + sy) * D_ + d_tile * 32 + tx];
        }
        __syncthreads();
        float* vtb = g_Vt + (size_t)bh * D_ * S_;
        #pragma unroll
        for (int i = 0; i < 4; i++) {
            int dy = ty + i * 8;
            vtb[(size_t)(d_tile * 32 + dy) * S_ + s_tile * 32 + tx] = t[dy][tx];
        }
    }
}

// ===================== main fused attention =====================
__global__ void __launch_bounds__(NT, 2)
attn_main(const float* __restrict__ q, const float* __restrict__ prev,
          const float* __restrict__ mask, const float* __restrict__ scale_p,
          float* __restrict__ out)
{
#ifdef HAS_TC
    extern __shared__ char smraw[];
    const uint32_t sb0 = smem_u32(smraw);
    const uint32_t sbase = (sb0 + 1023u) & ~1023u;
    char* sm = smraw + (sbase - sb0);

    const int tid = threadIdx.x;
    const int wid = tid >> 5;
    const int wg  = wid >> 2;                       // warpgroup -> LDTM col half
    const int r   = ((wid & 3) << 5) | (tid & 31);  // TMEM lane / row 0..127
    const int half = (tid & 31) >> 4;               // coalesced: half-warp
    const int cl   = tid & 15;                      // coalesced: col quad
    const int bh  = blockIdx.x >> 3;
    const int qb  = (blockIdx.x & 7) * 128;
    const float scale = *scale_p;

    float* outO = out;
    float* outW = out + OUT_O;
    float* outS = outW + OUT_W;
    float* lsum = (float*)(sm + OFF_LS);
    float* dt   = (float*)(sm + OFF_DT);

    const float4* qp4  = (const float4*)(q + ((size_t)bh * S_ + qb) * D_);
    const float4* ktp4 = (const float4*)(g_Kt + (size_t)bh * S_ * D_);
    const float*  vtb  = g_Vt + (size_t)bh * D_ * S_;

    if (tid == 0) {
        MBAR_INIT(sbase + OFF_MMA0, 1);
        MBAR_INIT(sbase + OFF_MMA1, 1);
        MBAR_INIT(sbase + OFF_CONS0, NT);
        MBAR_INIT(sbase + OFF_CONS1, NT);
        MBAR_INIT(sbase + OFF_MMA2, 1);
    }
    if (tid < 128) lsum[tid] = 0.0f;
    if (wid == 0) { TC_ALLOC(sbase + OFF_TM, 256); TC_RELINQ(); }
    __syncthreads();
    uint32_t tmem;
    asm volatile("ld.shared.b32 %0, [%1];" : "=r"(tmem) : "r"(sbase + OFF_TM));
    const uint32_t TM_D = tmem;         // 2 x 64 cols ping-pong
    const uint32_t TM_O = tmem + 128;   // 64 cols

    // ---- prefetch K chunk 0, then stage Q (bf16x2 split) ----
    float4 kreg[4];
    #pragma unroll
    for (int j = 0; j < 4; j++) kreg[j] = ktp4[tid + j * NT];
    #pragma unroll
    for (int j = 0; j < 8; j++) {
        int i = tid + j * NT;
        stage4(qp4[i], sm + OFF_A0, sm + OFF_A1, (uint32_t)i * 8u);
    }

    int phm0 = 0, phm1 = 0, phc0 = 0, phc1 = 0;

    // =============== Phase A: pipelined scores ===============
    for (int c = 0; c <= NCH; c++) {
        if (c < NCH) {
            const int b = c & 1;
            char* k0 = sm + OFF_B + (uint32_t)b * 16384u;
            char* k1 = k0 + 8192;
            #pragma unroll
            for (int j = 0; j < 4; j++)
                stage4(kreg[j], k0, k1, (uint32_t)(tid + j * NT) * 8u);
            if (c + 1 < NCH) {
                #pragma unroll
                for (int j = 0; j < 4; j++)
                    kreg[j] = ktp4[(c + 1) * 1024 + tid + j * NT];
            }
            FENCE_ASYNC();
            __syncthreads();
            if (tid == 0) {
                if (c >= 2) {
                    if (b == 0) { MBAR_WAIT(sbase + OFF_CONS0, phc0); phc0 ^= 1; }
                    else        { MBAR_WAIT(sbase + OFF_CONS1, phc1); phc1 ^= 1; }
                }
                issue_mma3(TM_D + (uint32_t)b * 64u,
                           sbase + OFF_A0, sbase + OFF_A1,
                           sbase + OFF_B + (uint32_t)b * 16384u,
                           sbase + OFF_B + (uint32_t)b * 16384u + 8192u, 0u);
                TC_COMMIT(sbase + ((b == 0) ? OFF_MMA0 : OFF_MMA1));
            }
        }
        if (c >= 1) {
            const int cc = c - 1, b2 = cc & 1;
            // warm L2 for the epilogue's prev/mask lines while MMA runs
            {
                size_t colb = (size_t)cc * 64 + cl * 4;
                #pragma unroll
                for (int j = 0; j < 8; j++) {
                    int rr = wid * 16 + 2 * j + half;
                    PREF_L2(prev + ((size_t)bh * S_ + qb + rr) * S_ + colb);
                }
            }
            if (b2 == 0) { MBAR_WAIT(sbase + OFF_MMA0, phm0); phm0 ^= 1; }
            else         { MBAR_WAIT(sbase + OFF_MMA1, phm1); phm1 ^= 1; }
            TC_FENCE_AFTER();
            uint32_t dr[32];
            TC_LD_X32(dr, TM_D + (uint32_t)b2 * 64u + (uint32_t)wg * 32u);
            TC_WAIT_LD();
            TC_FENCE_BEFORE();
            MBAR_ARRIVE(sbase + ((b2 == 0) ? OFF_CONS0 : OFF_CONS1));
            // guard: all dt readers of the PREVIOUS epilogue must drain
            __syncthreads();
            // transpose D to smem: row r, cols wg*32..+31, stride 65 (conflict-free)
            #pragma unroll
            for (int i = 0; i < 32; i++)
                dt[r * 65 + wg * 32 + i] = __uint_as_float(dr[i]);
            __syncthreads();
            // coalesced epilogue: warp wid owns rows wid*16..+15
            #pragma unroll
            for (int j = 0; j < 8; j++) {
                int rr = wid * 16 + 2 * j + half;
                size_t gr = (size_t)bh * S_ + qb + rr;
                size_t colb = (size_t)cc * 64 + cl * 4;
                float4 pv = *(const float4*)(prev + gr * S_ + colb);
                float4 mk = *(const float4*)(mask + (size_t)(qb + rr) * S_ + colb);
                int db = rr * 65 + cl * 4;
                float4 s;
                s.x = dt[db + 0] * mk.x * scale + pv.x;
                s.y = dt[db + 1] * mk.y * scale + pv.y;
                s.z = dt[db + 2] * mk.z * scale + pv.z;
                s.w = dt[db + 3] * mk.w * scale + pv.w;
                *(float4*)(outS + gr * S_ + colb) = s;
                float val = __expf(s.x) + __expf(s.y) + __expf(s.z) + __expf(s.w);
                val += __shfl_xor_sync(0xffffffffu, val, 1);
                val += __shfl_xor_sync(0xffffffffu, val, 2);
                val += __shfl_xor_sync(0xffffffffu, val, 4);
                val += __shfl_xor_sync(0xffffffffu, val, 8);
                if (cl == 0) lsum[rr] += val;
            }
        }
    }

    __syncthreads();
    if (tid < 128) lsum[tid] = 1.0f / lsum[tid];
    __syncthreads();

    // =============== Phase B: W + O (reverse order for L2) ===============
    float4 sreg[8], vreg[4];
    {
        #pragma unroll
        for (int j = 0; j < 8; j++) {
            int rr = wid * 16 + 2 * j + half;
            sreg[j] = *(const float4*)(outS + ((size_t)bh * S_ + qb + rr) * S_ + 15 * 64 + cl * 4);
        }
        #pragma unroll
        for (int j = 0; j < 4; j++) {
            int i = tid + j * NT;
            vreg[j] = *(const float4*)(vtb + (size_t)(i >> 4) * S_ + 15 * 64 + (i & 15) * 4);
        }
    }
    int ph2 = 0;
    for (int idx = 0; idx < NCH; idx++) {
        const int c = 15 - idx;
        float4 wv[8];
        #pragma unroll
        for (int j = 0; j < 8; j++) {
            int rr = wid * 16 + 2 * j + half;
            float il = lsum[rr];
            wv[j].x = __expf(sreg[j].x) * il;
            wv[j].y = __expf(sreg[j].y) * il;
            wv[j].z = __expf(sreg[j].z) * il;
            wv[j].w = __expf(sreg[j].w) * il;
            *(float4*)(outW + ((size_t)bh * S_ + qb + rr) * S_ + c * 64 + cl * 4) = wv[j];
        }
        if (idx > 0) { MBAR_WAIT(sbase + OFF_MMA2, ph2); ph2 ^= 1; }
        // stage W (A) and V (B) in coalesced layout
        #pragma unroll
        for (int j = 0; j < 8; j++) {
            int rr = wid * 16 + 2 * j + half;
            stage4(wv[j], sm + OFF_A0, sm + OFF_A1, (uint32_t)rr * 128u + (uint32_t)cl * 8u);
        }
        #pragma unroll
        for (int j = 0; j < 4; j++)
            stage4(vreg[j], sm + OFF_B, sm + OFF_B + 8192, (uint32_t)(tid + j * NT) * 8u);
        if (idx + 1 < NCH) {
            #pragma unroll
            for (int j = 0; j < 8; j++) {
                int rr = wid * 16 + 2 * j + half;
                sreg[j] = *(const float4*)(outS + ((size_t)bh * S_ + qb + rr) * S_ + (c - 1) * 64 + cl * 4);
            }
            #pragma unroll
            for (int j = 0; j < 4; j++) {
                int i = tid + j * NT;
                vreg[j] = *(const float4*)(vtb + (size_t)(i >> 4) * S_ + (c - 1) * 64 + (i & 15) * 4);
            }
        }
        FENCE_ASYNC();
        __syncthreads();
        if (tid == 0) {
            issue_mma3(TM_O, sbase + OFF_A0, sbase + OFF_A1,
                       sbase + OFF_B, sbase + OFF_B + 8192u, (idx == 0) ? 0u : 1u);
            TC_COMMIT(sbase + OFF_MMA2);
        }
    }

    // =============== O writeback ===============
    MBAR_WAIT(sbase + OFF_MMA2, ph2);
    TC_FENCE_AFTER();
    {
        uint32_t o[32];
        TC_LD_X32(o, TM_O + (uint32_t)wg * 32u);
        TC_WAIT_LD();
        float4* oo = (float4*)(outO + ((size_t)bh * S_ + qb + r) * D_ + wg * 32);
        #pragma unroll
        for (int j = 0; j < 8; j++)
            oo[j] = make_float4(__uint_as_float(o[4*j]), __uint_as_float(o[4*j+1]),
                                __uint_as_float(o[4*j+2]), __uint_as_float(o[4*j+3]));
    }
    TC_FENCE_BEFORE();
    __syncthreads();
    if (wid == 0) TC_DEALLOC(tmem, 256);
#endif  // HAS_TC
}

extern "C" void kernel_launch(void* const* d_in, const int* in_sizes, int n_in,
                              void* d_out, int out_size)
{
    const float* q     = (const float*)d_in[0];
    const float* k     = (const float*)d_in[1];
    const float* v     = (const float*)d_in[2];
    const float* prev  = (const float*)d_in[3];
    const float* mask  = (const float*)d_in[4];
    const float* scale = (const float*)d_in[5];
    float* out = (float*)d_out;

    dim3 tb(32, 8), tg(32, 4, BH_);
    transpose_kv<<<tg, tb>>>(k, v);

    cudaFuncSetAttribute(attn_main, cudaFuncAttributeMaxDynamicSharedMemorySize, SMEM_BYTES);
    attn_main<<<BH_ * 8, NT, SMEM_BYTES>>>(q, prev, mask, scale, out);
}

// round 9
// speedup vs baseline: 3.0323x; 1.1798x over previous
#include <cuda_runtime.h>
#include <cuda_bf16.h>
#include <cstdint>

#define B_   8
#define H_   16
#define S_   1024
#define D_   64
#define BH_  (B_*H_)
#define NT   256
#define NCH  16            // 64-col chunks

#define OUT_O ((size_t)BH_*S_*D_)
#define OUT_W ((size_t)BH_*S_*S_)

// pre-swizzled bf16 hi/lo MMA-ready tiles: 16KB per (bh, chunk)
__device__ uint4 g_Kst[BH_*NCH*1024];   // K tile: [64 s][64 d]
__device__ uint4 g_Vst[BH_*NCH*1024];   // V tile: [64 d][64 s]

// ---- smem (from 1KB-aligned base) ----
#define OFF_A0   0u        // Q hi | W hi (16K bf16 [128][64])
#define OFF_A1   16384u    // Q lo | W lo
#define OFF_B    32768u    // 2 x 16K tile buffers (hi 8K + lo 8K each): K (A) / V (B)
#define OFF_DT   65536u    // D transpose tile: 128 x 65 f32 = 33280
#define OFF_MISC 98816u
#define OFF_TM    (OFF_MISC + 0u)
#define OFF_KB0   (OFF_MISC + 8u)
#define OFF_KB1   (OFF_MISC + 16u)
#define OFF_MMA0  (OFF_MISC + 24u)
#define OFF_MMA1  (OFF_MISC + 32u)
#define OFF_CONS0 (OFF_MISC + 40u)
#define OFF_CONS1 (OFF_MISC + 48u)
#define OFF_MMA2  (OFF_MISC + 56u)
#define OFF_LS    (OFF_MISC + 64u)   // float[128]
#define SMEM_BYTES (OFF_MISC + 64u + 512u + 1024u)

#define IDESC_BF16_N64 ((1u<<4)|(1u<<7)|(1u<<10)|(8u<<17)|(8u<<24))
#define SWZ(o) ((o) ^ (((o) >> 3) & 0x70u))

#if defined(__CUDA_ARCH_FEAT_SM103_ALL) || defined(__CUDA_ARCH_FEAT_SM100_ALL)
#define HAS_TC 1
#endif

__device__ __forceinline__ uint32_t smem_u32(const void* p) {
    uint32_t a;
    asm("{ .reg .u64 t; cvta.to.shared.u64 t, %1; cvt.u32.u64 %0, t; }" : "=r"(a) : "l"(p));
    return a;
}
#define MBAR_INIT(a, n) asm volatile("mbarrier.init.shared.b64 [%0], %1;" :: "r"(a), "r"(n) : "memory")
#define MBAR_ARRIVE(a)  asm volatile("mbarrier.arrive.shared.b64 _, [%0];" :: "r"(a) : "memory")
#define MBAR_EXPECT(a, b) asm volatile("mbarrier.arrive.expect_tx.shared.b64 _, [%0], %1;" :: "r"(a), "r"(b) : "memory")
#define MBAR_WAIT(a, ph) do { \
    uint32_t _m = (a), _p = (ph), _d; \
    asm volatile("{ .reg .pred p; mbarrier.try_wait.parity.acquire.cta.shared::cta.b64 p, [%1], %2; selp.b32 %0,1,0,p; }" \
        : "=r"(_d) : "r"(_m), "r"(_p) : "memory"); \
    if (!_d) { \
        asm volatile("{ .reg .pred P1;\nWL_%=:\n mbarrier.try_wait.parity.acquire.cta.shared::cta.b64 P1, [%0], %1, 0x989680;\n @P1 bra.uni WD_%=;\n bra.uni WL_%=;\nWD_%=:\n}" \
            :: "r"(_m), "r"(_p) : "memory"); \
    } } while (0)
#define FENCE_ASYNC() asm volatile("fence.proxy.async.shared::cta;" ::: "memory")
#define BULK_G2S(dst, src, bytes, bar) \
    asm volatile("cp.async.bulk.shared::cluster.global.mbarrier::complete_tx::bytes [%0], [%1], %2, [%3];" \
        :: "r"(dst), "l"(src), "r"(bytes), "r"(bar) : "memory")

#ifdef HAS_TC
#define TC_ALLOC(a, n) asm volatile("tcgen05.alloc.cta_group::1.sync.aligned.shared::cta.b32 [%0], %1;" :: "r"(a), "r"(n) : "memory")
#define TC_RELINQ()    asm volatile("tcgen05.relinquish_alloc_permit.cta_group::1.sync.aligned;")
#define TC_DEALLOC(t, n) asm volatile("tcgen05.dealloc.cta_group::1.sync.aligned.b32 %0, %1;" :: "r"(t), "r"(n))
#define TC_COMMIT(bar) asm volatile("tcgen05.commit.cta_group::1.mbarrier::arrive::one.shared::cluster.b64 [%0];" :: "r"(bar) : "memory")
#define TC_WAIT_LD() asm volatile("tcgen05.wait::ld.sync.aligned;" ::: "memory")
#define TC_FENCE_BEFORE() asm volatile("tcgen05.fence::before_thread_sync;" ::: "memory")
#define TC_FENCE_AFTER()  asm volatile("tcgen05.fence::after_thread_sync;" ::: "memory")
#define TC_LD_X32(r, addr) \
    asm volatile("tcgen05.ld.sync.aligned.32x32b.x32.b32 " \
        "{%0,%1,%2,%3,%4,%5,%6,%7,%8,%9,%10,%11,%12,%13,%14,%15," \
        "%16,%17,%18,%19,%20,%21,%22,%23,%24,%25,%26,%27,%28,%29,%30,%31}, [%32];" \
        : "=r"((r)[0]),"=r"((r)[1]),"=r"((r)[2]),"=r"((r)[3]),"=r"((r)[4]),"=r"((r)[5]),"=r"((r)[6]),"=r"((r)[7]), \
          "=r"((r)[8]),"=r"((r)[9]),"=r"((r)[10]),"=r"((r)[11]),"=r"((r)[12]),"=r"((r)[13]),"=r"((r)[14]),"=r"((r)[15]), \
          "=r"((r)[16]),"=r"((r)[17]),"=r"((r)[18]),"=r"((r)[19]),"=r"((r)[20]),"=r"((r)[21]),"=r"((r)[22]),"=r"((r)[23]), \
          "=r"((r)[24]),"=r"((r)[25]),"=r"((r)[26]),"=r"((r)[27]),"=r"((r)[28]),"=r"((r)[29]),"=r"((r)[30]),"=r"((r)[31]) \
        : "r"(addr))

__device__ __forceinline__ void mma_bf16_ss(uint32_t d, uint64_t a, uint64_t b, uint32_t en) {
    asm volatile("{\n\t.reg .pred p;\n\tsetp.ne.u32 p, %4, 0;\n\t"
                 "tcgen05.mma.cta_group::1.kind::f16 [%0], %1, %2, %3, {%5,%5,%5,%5}, p;\n\t}"
                 :: "r"(d), "l"(a), "l"(b), "r"(IDESC_BF16_N64), "r"(en), "r"(0u) : "memory");
}
#endif

static __device__ __forceinline__ uint64_t mk_desc(uint32_t addr) {
    return (uint64_t(2) << 61) | (uint64_t(1) << 46) | (uint64_t(64) << 32) | (uint64_t(1) << 16)
         | ((uint64_t)(addr >> 4) & 0x3FFFull);
}

#ifdef HAS_TC
// 3-term bf16x3 MMA: A0B0 + A0B1 + A1B0, K=64 via 4 steps of 16
__device__ __forceinline__ void issue_mma3(uint32_t dtm, uint32_t a0, uint32_t a1,
                                           uint32_t b0, uint32_t b1, uint32_t accum_first) {
    uint64_t A0 = mk_desc(a0), A1 = mk_desc(a1), B0 = mk_desc(b0), B1 = mk_desc(b1);
    #pragma unroll
    for (int t = 0; t < 4; t++) mma_bf16_ss(dtm, A0 + t*2, B0 + t*2, (t > 0) ? 1u : accum_first);
    #pragma unroll
    for (int t = 0; t < 4; t++) mma_bf16_ss(dtm, A0 + t*2, B1 + t*2, 1u);
    #pragma unroll
    for (int t = 0; t < 4; t++) mma_bf16_ss(dtm, A1 + t*2, B0 + t*2, 1u);
}
#endif

__device__ __forceinline__ void cvt2(float x, float y, uint32_t& hw, uint32_t& lw) {
    __nv_bfloat162 h = __floats2bfloat162_rn(x, y);
    float hx = __bfloat162float(h.x), hy = __bfloat162float(h.y);
    __nv_bfloat162 l = __floats2bfloat162_rn(x - hx, y - hy);
    hw = *(uint32_t*)&h;
    lw = *(uint32_t*)&l;
}
__device__ __forceinline__ void stage4(float4 f, char* p0, char* p1, uint32_t off) {
    uint32_t h0, l0, h1, l1;
    cvt2(f.x, f.y, h0, l0);
    cvt2(f.z, f.w, h1, l1);
    uint32_t so = SWZ(off);
    *(uint2*)(p0 + so) = make_uint2(h0, h1);
    *(uint2*)(p1 + so) = make_uint2(l0, l1);
}

// ===================== pre-pass: K/V -> swizzled bf16 hi/lo tiles =====================
__global__ void prep_kv(const float* __restrict__ k, const float* __restrict__ v) {
    __shared__ uint8_t tile[16384];     // hi [0,8K), lo [8K,16K)
    const int c = blockIdx.x, which = blockIdx.y, bh = blockIdx.z;
    const int tid = threadIdx.x;
    if (which == 0) {
        const float4* k4 = (const float4*)(k + (size_t)bh * D_ * S_);
        for (int i = tid; i < 1024; i += 256) {
            int d = i >> 4, sq = i & 15;
            float4 f = k4[d * (S_/4) + c * 16 + sq];
            float vals[4] = {f.x, f.y, f.z, f.w};
            #pragma unroll
            for (int e = 0; e < 4; e++) {
                int s = sq * 4 + e;
                uint32_t off = SWZ((uint32_t)(s * 128 + d * 2));
                __nv_bfloat16 h = __float2bfloat16(vals[e]);
                __nv_bfloat16 l = __float2bfloat16(vals[e] - __bfloat162float(h));
                *(uint16_t*)(tile + off)        = *(uint16_t*)&h;
                *(uint16_t*)(tile + 8192 + off) = *(uint16_t*)&l;
            }
        }
        __syncthreads();
        uint4* dst = g_Kst + ((size_t)bh * NCH + c) * 1024;
        const uint4* t4 = (const uint4*)tile;
        for (int i = tid; i < 1024; i += 256) dst[i] = t4[i];
    } else {
        const float4* v4 = (const float4*)(v + (size_t)bh * S_ * D_);
        for (int i = tid; i < 1024; i += 256) {
            int s = i >> 4, dq = i & 15;
            float4 f = v4[(c * 64 + s) * (D_/4) + dq];
            float vals[4] = {f.x, f.y, f.z, f.w};
            #pragma unroll
            for (int e = 0; e < 4; e++) {
                int d = dq * 4 + e;
                uint32_t off = SWZ((uint32_t)(d * 128 + s * 2));
                __nv_bfloat16 h = __float2bfloat16(vals[e]);
                __nv_bfloat16 l = __float2bfloat16(vals[e] - __bfloat162float(h));
                *(uint16_t*)(tile + off)        = *(uint16_t*)&h;
                *(uint16_t*)(tile + 8192 + off) = *(uint16_t*)&l;
            }
        }
        __syncthreads();
        uint4* dst = g_Vst + ((size_t)bh * NCH + c) * 1024;
        const uint4* t4 = (const uint4*)tile;
        for (int i = tid; i < 1024; i += 256) dst[i] = t4[i];
    }
}

// ===================== main fused attention =====================
__global__ void __launch_bounds__(NT, 2)
attn_main(const float* __restrict__ q, const float* __restrict__ prev,
          const float* __restrict__ mask, const float* __restrict__ scale_p,
          float* __restrict__ out)
{
#ifdef HAS_TC
    extern __shared__ char smraw[];
    const uint32_t sb0 = smem_u32(smraw);
    const uint32_t sbase = (sb0 + 1023u) & ~1023u;
    char* sm = smraw + (sbase - sb0);

    const int tid = threadIdx.x;
    const int wid = tid >> 5;
    const int wg  = wid >> 2;
    const int r   = ((wid & 3) << 5) | (tid & 31);
    const int half = (tid & 31) >> 4;
    const int cl   = tid & 15;
    const int bh  = blockIdx.x >> 3;
    const int qb  = (blockIdx.x & 7) * 128;
    const float scale = *scale_p;

    float* outO = out;
    float* outW = out + OUT_O;
    float* outS = outW + OUT_W;
    float* lsum = (float*)(sm + OFF_LS);
    float* dt   = (float*)(sm + OFF_DT);

    const float4* qp4 = (const float4*)(q + ((size_t)bh * S_ + qb) * D_);
    const char* kst = (const char*)(g_Kst + (size_t)bh * NCH * 1024);
    const char* vst = (const char*)(g_Vst + (size_t)bh * NCH * 1024);

    if (tid == 0) {
        MBAR_INIT(sbase + OFF_KB0, 1);
        MBAR_INIT(sbase + OFF_KB1, 1);
        MBAR_INIT(sbase + OFF_MMA0, 1);
        MBAR_INIT(sbase + OFF_MMA1, 1);
        MBAR_INIT(sbase + OFF_CONS0, NT);
        MBAR_INIT(sbase + OFF_CONS1, NT);
        MBAR_INIT(sbase + OFF_MMA2, 1);
    }
    if (tid < 128) lsum[tid] = 0.0f;
    if (wid == 0) { TC_ALLOC(sbase + OFF_TM, 256); TC_RELINQ(); }
    __syncthreads();
    uint32_t tmem;
    asm volatile("ld.shared.b32 %0, [%1];" : "=r"(tmem) : "r"(sbase + OFF_TM));
    const uint32_t TM_D = tmem;
    const uint32_t TM_O = tmem + 128;

    // bulk-load K chunks 0,1 (tid0); stage Q (all threads)
    if (tid == 0) {
        MBAR_EXPECT(sbase + OFF_KB0, 16384);
        BULK_G2S(sbase + OFF_B, kst, 16384, sbase + OFF_KB0);
        MBAR_EXPECT(sbase + OFF_KB1, 16384);
        BULK_G2S(sbase + OFF_B + 16384u, kst + 16384, 16384, sbase + OFF_KB1);
    }
    #pragma unroll
    for (int j = 0; j < 8; j++) {
        int i = tid + j * NT;
        stage4(qp4[i], sm + OFF_A0, sm + OFF_A1, (uint32_t)i * 8u);
    }
    FENCE_ASYNC();
    __syncthreads();

    int phm0 = 0, phm1 = 0, phc0 = 0, phc1 = 0;

    // =============== Phase A ===============
    for (int c = 0; c <= NCH; c++) {
        if (c < NCH && tid == 0) {
            const int b = c & 1;
            MBAR_WAIT(sbase + (b ? OFF_KB1 : OFF_KB0), (c >> 1) & 1);
            if (c >= 2) {
                if (b == 0) { MBAR_WAIT(sbase + OFF_CONS0, phc0); phc0 ^= 1; }
                else        { MBAR_WAIT(sbase + OFF_CONS1, phc1); phc1 ^= 1; }
            }
            issue_mma3(TM_D + (uint32_t)b * 64u, sbase + OFF_A0, sbase + OFF_A1,
                       sbase + OFF_B + (uint32_t)b * 16384u,
                       sbase + OFF_B + (uint32_t)b * 16384u + 8192u, 0u);
            TC_COMMIT(sbase + (b ? OFF_MMA1 : OFF_MMA0));
        }
        if (c >= 1) {
            const int cc = c - 1, b2 = cc & 1;
            // issue prev loads before the MMA wait (latency absorbed)
            float4 pv[8];
            {
                size_t colb = (size_t)cc * 64 + cl * 4;
                #pragma unroll
                for (int j = 0; j < 8; j++) {
                    int rr = wid * 16 + 2 * j + half;
                    pv[j] = *(const float4*)(prev + ((size_t)bh * S_ + qb + rr) * S_ + colb);
                }
            }
            if (b2 == 0) { MBAR_WAIT(sbase + OFF_MMA0, phm0); phm0 ^= 1; }
            else         { MBAR_WAIT(sbase + OFF_MMA1, phm1); phm1 ^= 1; }
            if (tid == 0) {
                if (cc + 2 < NCH) {      // refill K(cc+2) into freed buf
                    uint32_t kb = sbase + ((cc & 1) ? OFF_KB1 : OFF_KB0);
                    MBAR_EXPECT(kb, 16384);
                    BULK_G2S(sbase + OFF_B + (uint32_t)(cc & 1) * 16384u,
                             kst + (size_t)(cc + 2) * 16384, 16384, kb);
                } else {                 // pre-issue Phase-B V tiles into freed bufs
                    uint32_t vb = sbase + ((cc == 14) ? OFF_KB0 : OFF_KB1);
                    int vidx = (cc == 14) ? 0 : 1;          // idx0->chunk15, idx1->chunk14
                    MBAR_EXPECT(vb, 16384);
                    BULK_G2S(sbase + OFF_B + (uint32_t)(vidx & 1) * 16384u,
                             vst + (size_t)(15 - vidx) * 16384, 16384, vb);
                }
            }
            TC_FENCE_AFTER();
            uint32_t dr[32];
            TC_LD_X32(dr, TM_D + (uint32_t)b2 * 64u + (uint32_t)wg * 32u);
            TC_WAIT_LD();
            TC_FENCE_BEFORE();
            MBAR_ARRIVE(sbase + (b2 ? OFF_CONS1 : OFF_CONS0));
            __syncthreads();            // previous epilogue's dt readers drained
            #pragma unroll
            for (int i = 0; i < 32; i++)
                dt[r * 65 + wg * 32 + i] = __uint_as_float(dr[i]);
            __syncthreads();
            #pragma unroll
            for (int j = 0; j < 8; j++) {
                int rr = wid * 16 + 2 * j + half;
                size_t gr = (size_t)bh * S_ + qb + rr;
                size_t colb = (size_t)cc * 64 + cl * 4;
                float4 mk = *(const float4*)(mask + (size_t)(qb + rr) * S_ + colb);
                int db = rr * 65 + cl * 4;
                float4 s;
                s.x = dt[db + 0] * mk.x * scale + pv[j].x;
                s.y = dt[db + 1] * mk.y * scale + pv[j].y;
                s.z = dt[db + 2] * mk.z * scale + pv[j].z;
                s.w = dt[db + 3] * mk.w * scale + pv[j].w;
                *(float4*)(outS + gr * S_ + colb) = s;
                float val = __expf(s.x) + __expf(s.y) + __expf(s.z) + __expf(s.w);
                val += __shfl_xor_sync(0xffffffffu, val, 1);
                val += __shfl_xor_sync(0xffffffffu, val, 2);
                val += __shfl_xor_sync(0xffffffffu, val, 4);
                val += __shfl_xor_sync(0xffffffffu, val, 8);
                if (cl == 0) lsum[rr] += val;
            }
        }
    }

    __syncthreads();
    if (tid < 128) lsum[tid] = 1.0f / lsum[tid];
    __syncthreads();

    // =============== Phase B: reverse chunk order ===============
    float4 sreg[8];
    #pragma unroll
    for (int j = 0; j < 8; j++) {
        int rr = wid * 16 + 2 * j + half;
        sreg[j] = *(const float4*)(outS + ((size_t)bh * S_ + qb + rr) * S_ + 15 * 64 + cl * 4);
    }
    int ph2 = 0;
    for (int idx = 0; idx < NCH; idx++) {
        const int c = 15 - idx;
        float4 wv[8];
        #pragma unroll
        for (int j = 0; j < 8; j++) {
            int rr = wid * 16 + 2 * j + half;
            float il = lsum[rr];
            wv[j].x = __expf(sreg[j].x) * il;
            wv[j].y = __expf(sreg[j].y) * il;
            wv[j].z = __expf(sreg[j].z) * il;
            wv[j].w = __expf(sreg[j].w) * il;
            *(float4*)(outW + ((size_t)bh * S_ + qb + rr) * S_ + c * 64 + cl * 4) = wv[j];
        }
        if (idx > 0) { MBAR_WAIT(sbase + OFF_MMA2, ph2); ph2 ^= 1; }
        if (tid == 0 && idx >= 1 && idx + 1 < NCH) {   // refill V(idx+1)
            uint32_t vb = sbase + (((idx + 1) & 1) ? OFF_KB1 : OFF_KB0);
            MBAR_EXPECT(vb, 16384);
            BULK_G2S(sbase + OFF_B + (uint32_t)((idx + 1) & 1) * 16384u,
                     vst + (size_t)(15 - (idx + 1)) * 16384, 16384, vb);
        }
        #pragma unroll
        for (int j = 0; j < 8; j++) {
            int rr = wid * 16 + 2 * j + half;
            stage4(wv[j], sm + OFF_A0, sm + OFF_A1, (uint32_t)rr * 128u + (uint32_t)cl * 8u);
        }
        if (idx + 1 < NCH) {
            #pragma unroll
            for (int j = 0; j < 8; j++) {
                int rr = wid * 16 + 2 * j + half;
                sreg[j] = *(const float4*)(outS + ((size_t)bh * S_ + qb + rr) * S_ + (c - 1) * 64 + cl * 4);
            }
        }
        FENCE_ASYNC();
        __syncthreads();
        if (tid == 0) {
            MBAR_WAIT(sbase + ((idx & 1) ? OFF_KB1 : OFF_KB0), (idx >> 1) & 1);
            issue_mma3(TM_O, sbase + OFF_A0, sbase + OFF_A1,
                       sbase + OFF_B + (uint32_t)(idx & 1) * 16384u,
                       sbase + OFF_B + (uint32_t)(idx & 1) * 16384u + 8192u,
                       (idx == 0) ? 0u : 1u);
            TC_COMMIT(sbase + OFF_MMA2);
        }
    }

    // =============== O writeback ===============
    MBAR_WAIT(sbase + OFF_MMA2, ph2);
    TC_FENCE_AFTER();
    {
        uint32_t o[32];
        TC_LD_X32(o, TM_O + (uint32_t)wg * 32u);
        TC_WAIT_LD();
        float4* oo = (float4*)(outO + ((size_t)bh * S_ + qb + r) * D_ + wg * 32);
        #pragma unroll
        for (int j = 0; j < 8; j++)
            oo[j] = make_float4(__uint_as_float(o[4*j]), __uint_as_float(o[4*j+1]),
                                __uint_as_float(o[4*j+2]), __uint_as_float(o[4*j+3]));
    }
    TC_FENCE_BEFORE();
    __syncthreads();
    if (wid == 0) TC_DEALLOC(tmem, 256);
#endif  // HAS_TC
}

extern "C" void kernel_launch(void* const* d_in, const int* in_sizes, int n_in,
                              void* d_out, int out_size)
{
    const float* q     = (const float*)d_in[0];
    const float* k     = (const float*)d_in[1];
    const float* v     = (const float*)d_in[2];
    const float* prev  = (const float*)d_in[3];
    const float* mask  = (const float*)d_in[4];
    const float* scale = (const float*)d_in[5];
    float* out = (float*)d_out;

    dim3 pg(NCH, 2, BH_);
    prep_kv<<<pg, 256>>>(k, v);

    cudaFuncSetAttribute(attn_main, cudaFuncAttributeMaxDynamicSharedMemorySize, SMEM_BYTES);
    attn_main<<<BH_ * 8, NT, SMEM_BYTES>>>(q, prev, mask, scale, out);
}